// round 2
// baseline (speedup 1.0000x reference)
#include <cuda_runtime.h>
#include <cuda_bf16.h>
#include <math.h>

// Problem constants
#define BATCH 8
#define CDIM 384
#define NHEAD 8
#define CH 48          // channels per head
#define HW 16384       // h*w = 128*128
#define EPS 1e-12f

// ---------------- scratch (device globals; allocation-free rule) ----------------
__device__ float g_q[(size_t)BATCH * CDIM * HW];
__device__ float g_k[(size_t)BATCH * CDIM * HW];
__device__ float g_v[(size_t)BATCH * CDIM * HW];
__device__ float g_invq[BATCH * CDIM];
__device__ float g_invk[BATCH * CDIM];
__device__ float g_S[BATCH * NHEAD * CH * CH];   // attn logits (accumulated via atomics)
__device__ float g_A[BATCH * NHEAD * CH * CH];   // softmaxed attn
__device__ float g_W[BATCH * CDIM * CDIM];       // wo @ blockdiag(A)

// ---------------- kernel 0: zero the atomic accumulator ----------------
__global__ void zero_S_kernel() {
    int i = blockIdx.x * blockDim.x + threadIdx.x;
    if (i < BATCH * NHEAD * CH * CH) g_S[i] = 0.f;
}

// ---------------- kernel 1: fused QKV projection GEMM ----------------
// Y[proj][b][o][n] = sum_c W_proj[o][c] * x[b][c][n]
// grid: (HW/128, 9, BATCH)  block: 256, 128x128 tile, BK=8, 8x8 per thread
__global__ __launch_bounds__(256) void qkv_gemm(
    const float* __restrict__ x,
    const float* __restrict__ wq,
    const float* __restrict__ wk,
    const float* __restrict__ wv)
{
    const int bn = blockIdx.x * 128;
    const int proj = blockIdx.y / 3;                // 0=q,1=k,2=v (tiles never straddle)
    const int obase = (blockIdx.y % 3) * 128;
    const int b = blockIdx.z;
    const int tid = threadIdx.x;

    const float* __restrict__ w = (proj == 0) ? wq : (proj == 1) ? wk : wv;

    __shared__ float As[8][128];
    __shared__ float Bs[8][128];

    // A tile load mapping: 128 rows x 8 k, one float4 per thread
    const int arow = tid >> 1;
    const int acol = (tid & 1) * 4;
    const float* aptr = w + (size_t)(obase + arow) * CDIM + acol;

    // B tile load mapping: 8 k-rows x 128 n, one float4 per thread
    const int brow = tid >> 5;
    const int bcol = (tid & 31) * 4;
    const float* bptr = x + ((size_t)b * CDIM + brow) * HW + bn + bcol;

    const int rowBase = (tid >> 4) * 8;
    const int colBase = (tid & 15) * 8;

    float acc[8][8];
#pragma unroll
    for (int i = 0; i < 8; ++i)
#pragma unroll
        for (int j = 0; j < 8; ++j) acc[i][j] = 0.f;

    for (int kt = 0; kt < CDIM / 8; ++kt) {
        float4 av = *(const float4*)(aptr + kt * 8);
        As[acol + 0][arow] = av.x;
        As[acol + 1][arow] = av.y;
        As[acol + 2][arow] = av.z;
        As[acol + 3][arow] = av.w;
        float4 bv = *(const float4*)(bptr + (size_t)kt * 8 * HW);
        *(float4*)&Bs[brow][bcol] = bv;
        __syncthreads();
#pragma unroll
        for (int kk = 0; kk < 8; ++kk) {
            float4 a0 = *(const float4*)&As[kk][rowBase];
            float4 a1 = *(const float4*)&As[kk][rowBase + 4];
            float4 b0 = *(const float4*)&Bs[kk][colBase];
            float4 b1 = *(const float4*)&Bs[kk][colBase + 4];
            float ar[8] = {a0.x, a0.y, a0.z, a0.w, a1.x, a1.y, a1.z, a1.w};
            float br[8] = {b0.x, b0.y, b0.z, b0.w, b1.x, b1.y, b1.z, b1.w};
#pragma unroll
            for (int i = 0; i < 8; ++i)
#pragma unroll
                for (int j = 0; j < 8; ++j) acc[i][j] = fmaf(ar[i], br[j], acc[i][j]);
        }
        __syncthreads();
    }

    float* dst = (proj == 0) ? g_q : (proj == 1) ? g_k : g_v;
#pragma unroll
    for (int i = 0; i < 8; ++i) {
        int o = obase + rowBase + i;
        float* p = dst + ((size_t)b * CDIM + o) * HW + bn + colBase;
        *(float4*)p       = make_float4(acc[i][0], acc[i][1], acc[i][2], acc[i][3]);
        *(float4*)(p + 4) = make_float4(acc[i][4], acc[i][5], acc[i][6], acc[i][7]);
    }
}

// ---------------- kernel 2: per-row inverse norms for q and k ----------------
// grid: (BATCH*CDIM, 2)   block: 256
__global__ __launch_bounds__(256) void rownorm_kernel() {
    const int row = blockIdx.x;                  // 0..3071 = b*384 + c'
    const int which = blockIdx.y;                // 0=q, 1=k
    const float* src = (which ? g_k : g_q) + (size_t)row * HW;
    const int tid = threadIdx.x;

    float local = 0.f;
    const float4* src4 = (const float4*)src;
    for (int i = tid; i < HW / 4; i += 256) {
        float4 v = src4[i];
        local = fmaf(v.x, v.x, local);
        local = fmaf(v.y, v.y, local);
        local = fmaf(v.z, v.z, local);
        local = fmaf(v.w, v.w, local);
    }
    __shared__ float red[256];
    red[tid] = local;
    __syncthreads();
    for (int s = 128; s > 0; s >>= 1) {
        if (tid < s) red[tid] += red[tid + s];
        __syncthreads();
    }
    if (tid == 0) {
        float inv = 1.f / fmaxf(sqrtf(red[0]), EPS);
        if (which) g_invk[row] = inv; else g_invq[row] = inv;
    }
}

// ---------------- kernel 3: split-K attn logits  S = q @ k^T  ----------------
// grid: (BATCH*NHEAD, 16)  block: 256; each block handles 1024 of the 16384 K.
__global__ __launch_bounds__(256) void attn_partial_kernel() {
    const int bh = blockIdx.x;           // b*8 + h
    const int b = bh >> 3;
    const int h = bh & 7;
    const int kbase = blockIdx.y * 1024;
    const int tid = threadIdx.x;

    __shared__ float qs[CH][68];
    __shared__ float ks[CH][68];

    const int c0 = (tid >> 4) * 3;
    const int d0 = (tid & 15) * 3;

    float acc[3][3];
#pragma unroll
    for (int i = 0; i < 3; ++i)
#pragma unroll
        for (int j = 0; j < 3; ++j) acc[i][j] = 0.f;

    const size_t rowstart = (size_t)(b * CDIM + h * CH);

    for (int ck = 0; ck < 16; ++ck) {
        const int koff = kbase + ck * 64;
        // load 48x64 q and k tiles (3 float4 per thread per matrix)
#pragma unroll
        for (int t = 0; t < 3; ++t) {
            int idx = t * 256 + tid;      // 0..767
            int row = idx >> 4;           // 0..47
            int col = (idx & 15) * 4;     // 0..60
            float4 qv = *(const float4*)(g_q + (rowstart + row) * HW + koff + col);
            float4 kv = *(const float4*)(g_k + (rowstart + row) * HW + koff + col);
            *(float4*)&qs[row][col] = qv;
            *(float4*)&ks[row][col] = kv;
        }
        __syncthreads();
#pragma unroll 8
        for (int kk = 0; kk < 64; ++kk) {
            float q0 = qs[c0 + 0][kk], q1 = qs[c0 + 1][kk], q2 = qs[c0 + 2][kk];
            float k0 = ks[d0 + 0][kk], k1 = ks[d0 + 1][kk], k2 = ks[d0 + 2][kk];
            acc[0][0] = fmaf(q0, k0, acc[0][0]);
            acc[0][1] = fmaf(q0, k1, acc[0][1]);
            acc[0][2] = fmaf(q0, k2, acc[0][2]);
            acc[1][0] = fmaf(q1, k0, acc[1][0]);
            acc[1][1] = fmaf(q1, k1, acc[1][1]);
            acc[1][2] = fmaf(q1, k2, acc[1][2]);
            acc[2][0] = fmaf(q2, k0, acc[2][0]);
            acc[2][1] = fmaf(q2, k1, acc[2][1]);
            acc[2][2] = fmaf(q2, k2, acc[2][2]);
        }
        __syncthreads();
    }

    float* Sb = g_S + (size_t)bh * CH * CH;
#pragma unroll
    for (int i = 0; i < 3; ++i)
#pragma unroll
        for (int j = 0; j < 3; ++j)
            atomicAdd(&Sb[(c0 + i) * CH + (d0 + j)], acc[i][j]);
}

// ---------------- kernel 4: scale (temp * invq * invk) + softmax ----------------
// grid: 64  block: 64 (48 active lanes, one row each)
__global__ void attn_softmax_kernel(const float* __restrict__ temperature) {
    const int bh = blockIdx.x;
    const int b = bh >> 3;
    const int h = bh & 7;
    const int c = threadIdx.x;
    if (c >= CH) return;

    const float t = temperature[h];
    const float sq = g_invq[b * CDIM + h * CH + c] * t;
    const float* Srow = g_S + (size_t)bh * CH * CH + c * CH;
    const float* ik = g_invk + b * CDIM + h * CH;

    float v[CH];
    float m = -1e30f;
#pragma unroll
    for (int d = 0; d < CH; ++d) {
        v[d] = Srow[d] * sq * ik[d];
        m = fmaxf(m, v[d]);
    }
    float sum = 0.f;
#pragma unroll
    for (int d = 0; d < CH; ++d) {
        v[d] = __expf(v[d] - m);
        sum += v[d];
    }
    float inv = 1.f / sum;
    float* Arow = g_A + (size_t)bh * CH * CH + c * CH;
#pragma unroll
    for (int d = 0; d < CH; ++d) Arow[d] = v[d] * inv;
}

// ---------------- kernel 5: W_b = wo @ blockdiag(A_b) ----------------
// grid: (BATCH, CDIM)  block: 384   W[b][o][h*48+d] = sum_c wo[o][h*48+c]*A[b,h,c,d]
__global__ __launch_bounds__(384) void make_W_kernel(const float* __restrict__ wo) {
    const int b = blockIdx.x;
    const int o = blockIdx.y;
    const int m = threadIdx.x;       // 0..383
    const int h = m / CH;
    const int d = m % CH;

    const float* worow = wo + (size_t)o * CDIM + h * CH;
    const float* Ab = g_A + ((size_t)(b * NHEAD + h)) * CH * CH;

    float acc = 0.f;
#pragma unroll
    for (int c = 0; c < CH; ++c)
        acc = fmaf(worow[c], Ab[c * CH + d], acc);
    g_W[((size_t)b * CDIM + o) * CDIM + m] = acc;
}

// ---------------- kernel 6: out_b = W_b @ v_b ----------------
// grid: (HW/128, 3, BATCH) block: 256 — same tiling as qkv_gemm
__global__ __launch_bounds__(256) void out_gemm(float* __restrict__ out) {
    const int bn = blockIdx.x * 128;
    const int obase = blockIdx.y * 128;
    const int b = blockIdx.z;
    const int tid = threadIdx.x;

    const float* __restrict__ A = g_W + (size_t)b * CDIM * CDIM;

    __shared__ float As[8][128];
    __shared__ float Bs[8][128];

    const int arow = tid >> 1;
    const int acol = (tid & 1) * 4;
    const float* aptr = A + (size_t)(obase + arow) * CDIM + acol;

    const int brow = tid >> 5;
    const int bcol = (tid & 31) * 4;
    const float* bptr = g_v + ((size_t)b * CDIM + brow) * HW + bn + bcol;

    const int rowBase = (tid >> 4) * 8;
    const int colBase = (tid & 15) * 8;

    float acc[8][8];
#pragma unroll
    for (int i = 0; i < 8; ++i)
#pragma unroll
        for (int j = 0; j < 8; ++j) acc[i][j] = 0.f;

    for (int kt = 0; kt < CDIM / 8; ++kt) {
        float4 av = *(const float4*)(aptr + kt * 8);
        As[acol + 0][arow] = av.x;
        As[acol + 1][arow] = av.y;
        As[acol + 2][arow] = av.z;
        As[acol + 3][arow] = av.w;
        float4 bv = *(const float4*)(bptr + (size_t)kt * 8 * HW);
        *(float4*)&Bs[brow][bcol] = bv;
        __syncthreads();
#pragma unroll
        for (int kk = 0; kk < 8; ++kk) {
            float4 a0 = *(const float4*)&As[kk][rowBase];
            float4 a1 = *(const float4*)&As[kk][rowBase + 4];
            float4 b0 = *(const float4*)&Bs[kk][colBase];
            float4 b1 = *(const float4*)&Bs[kk][colBase + 4];
            float ar[8] = {a0.x, a0.y, a0.z, a0.w, a1.x, a1.y, a1.z, a1.w};
            float br[8] = {b0.x, b0.y, b0.z, b0.w, b1.x, b1.y, b1.z, b1.w};
#pragma unroll
            for (int i = 0; i < 8; ++i)
#pragma unroll
                for (int j = 0; j < 8; ++j) acc[i][j] = fmaf(ar[i], br[j], acc[i][j]);
        }
        __syncthreads();
    }

#pragma unroll
    for (int i = 0; i < 8; ++i) {
        int o = obase + rowBase + i;
        float* p = out + ((size_t)b * CDIM + o) * HW + bn + colBase;
        *(float4*)p       = make_float4(acc[i][0], acc[i][1], acc[i][2], acc[i][3]);
        *(float4*)(p + 4) = make_float4(acc[i][4], acc[i][5], acc[i][6], acc[i][7]);
    }
}

// ---------------- launcher ----------------
extern "C" void kernel_launch(void* const* d_in, const int* in_sizes, int n_in,
                              void* d_out, int out_size) {
    const float* x    = (const float*)d_in[0];
    const float* wq   = (const float*)d_in[1];
    const float* wk   = (const float*)d_in[2];
    const float* wv   = (const float*)d_in[3];
    const float* wo   = (const float*)d_in[4];
    const float* temp = (const float*)d_in[5];
    float* out = (float*)d_out;

    zero_S_kernel<<<(BATCH * NHEAD * CH * CH + 255) / 256, 256>>>();
    qkv_gemm<<<dim3(HW / 128, 9, BATCH), 256>>>(x, wq, wk, wv);
    rownorm_kernel<<<dim3(BATCH * CDIM, 2), 256>>>();
    attn_partial_kernel<<<dim3(BATCH * NHEAD, 16), 256>>>();
    attn_softmax_kernel<<<BATCH * NHEAD, 64>>>(temp);
    make_W_kernel<<<dim3(BATCH, CDIM), 384>>>(wo);
    out_gemm<<<dim3(HW / 128, 3, BATCH), 256>>>(out);
}

// round 4
// speedup vs baseline: 1.9837x; 1.9837x over previous
#include <cuda_runtime.h>
#include <cuda_bf16.h>
#include <math.h>

#define BATCH 8
#define CDIM 384
#define NHEAD 8
#define CH 48
#define HW 16384
#define EPS 1e-12f

// ---------------- scratch ----------------
__device__ float g_G [(size_t)BATCH * CDIM * CDIM];   // x x^T per batch (symmetric)
__device__ float g_Rq[(size_t)BATCH * CDIM * CDIM];   // Wq @ G
__device__ float g_Rk[(size_t)BATCH * CDIM * CDIM];   // Wk @ G
__device__ float g_invq[BATCH * CDIM];
__device__ float g_invk[BATCH * CDIM];
__device__ float g_S [BATCH * NHEAD * CH * CH];
__device__ float g_A [BATCH * NHEAD * CH * CH];
__device__ float g_Bs[(size_t)BATCH * CDIM * CDIM];   // blockdiag(A) @ Wv
__device__ float g_M [(size_t)BATCH * CDIM * CDIM];   // wo @ g_Bs

// ---------------- kernel: zero G (atomic accumulator) ----------------
__global__ void zero_G_kernel() {
    size_t i = (size_t)blockIdx.x * 256 + threadIdx.x;
    if (i < (size_t)BATCH * CDIM * CDIM) g_G[i] = 0.f;
}

// ---------------- kernel: G = x x^T  (upper tile-triangle, split-K atomics) ----------------
// grid: (6 tile-pairs, 16 k-splits, BATCH), block 256. 128x128 tile, BK=8.
__global__ __launch_bounds__(256) void syrk_kernel(const float* __restrict__ x) {
    const int TI[6] = {0, 0, 0, 1, 1, 2};
    const int TJ[6] = {0, 1, 2, 1, 2, 2};
    const int ti = TI[blockIdx.x], tj = TJ[blockIdx.x];
    const int b = blockIdx.z;
    const int koff0 = blockIdx.y * 1024;
    const int tid = threadIdx.x;

    __shared__ float As[8][128];
    __shared__ float Bs[8][128];

    const int lrow = tid >> 1;
    const int lkc = (tid & 1) * 4;
    const float* aptr = x + ((size_t)b * CDIM + ti * 128 + lrow) * HW + koff0 + lkc;
    const float* bptr = x + ((size_t)b * CDIM + tj * 128 + lrow) * HW + koff0 + lkc;

    const int rowBase = (tid >> 4) * 8;
    const int colBase = (tid & 15) * 8;

    float acc[8][8];
#pragma unroll
    for (int i = 0; i < 8; ++i)
#pragma unroll
        for (int j = 0; j < 8; ++j) acc[i][j] = 0.f;

    for (int it = 0; it < 128; ++it) {
        float4 av = *(const float4*)(aptr + it * 8);
        float4 bv = *(const float4*)(bptr + it * 8);
        As[lkc + 0][lrow] = av.x; As[lkc + 1][lrow] = av.y;
        As[lkc + 2][lrow] = av.z; As[lkc + 3][lrow] = av.w;
        Bs[lkc + 0][lrow] = bv.x; Bs[lkc + 1][lrow] = bv.y;
        Bs[lkc + 2][lrow] = bv.z; Bs[lkc + 3][lrow] = bv.w;
        __syncthreads();
#pragma unroll
        for (int kk = 0; kk < 8; ++kk) {
            float4 a0 = *(const float4*)&As[kk][rowBase];
            float4 a1 = *(const float4*)&As[kk][rowBase + 4];
            float4 b0 = *(const float4*)&Bs[kk][colBase];
            float4 b1 = *(const float4*)&Bs[kk][colBase + 4];
            float ar[8] = {a0.x, a0.y, a0.z, a0.w, a1.x, a1.y, a1.z, a1.w};
            float br[8] = {b0.x, b0.y, b0.z, b0.w, b1.x, b1.y, b1.z, b1.w};
#pragma unroll
            for (int i = 0; i < 8; ++i)
#pragma unroll
                for (int j = 0; j < 8; ++j) acc[i][j] = fmaf(ar[i], br[j], acc[i][j]);
        }
        __syncthreads();
    }

    float* Gp = g_G + (size_t)b * CDIM * CDIM;
#pragma unroll
    for (int i = 0; i < 8; ++i)
#pragma unroll
        for (int j = 0; j < 8; ++j)
            atomicAdd(&Gp[(size_t)(ti * 128 + rowBase + i) * CDIM + tj * 128 + colBase + j],
                      acc[i][j]);
}

// ---------------- kernel: mirror lower tile-triangle of G ----------------
__global__ void mirror_G_kernel() {
    size_t i = (size_t)blockIdx.x * 256 + threadIdx.x;
    if (i >= (size_t)BATCH * CDIM * CDIM) return;
    size_t bb = i / (CDIM * CDIM);
    int rc = (int)(i % (CDIM * CDIM));
    int r = rc / CDIM, c = rc % CDIM;
    if ((r >> 7) > (c >> 7))
        g_G[i] = g_G[bb * CDIM * CDIM + (size_t)c * CDIM + r];
}

// ---------------- kernel: small GEMM with device-resolved scratch pointers ----------------
// mode 0: C=g_Rq, B=g_G   (A = wq)
// mode 1: C=g_Rk, B=g_G   (A = wk)
// mode 2: C=g_M,  B=g_Bs  (A = wo)
// grid: (36, BATCH)  block 256; 64x64 tile, BK=16, 4x4 micro. A is shared across batch.
__global__ __launch_bounds__(256) void small_gemm(const float* __restrict__ A, int mode)
{
    const int m0 = (blockIdx.x % 6) * 64;
    const int n0 = (blockIdx.x / 6) * 64;
    const size_t z = blockIdx.y;
    const size_t CC = (size_t)CDIM * CDIM;

    const float* __restrict__ B = ((mode == 2) ? g_Bs : g_G) + z * CC;
    float* __restrict__ C = ((mode == 0) ? g_Rq : (mode == 1) ? g_Rk : g_M) + z * CC;

    __shared__ float Asm[16][68];
    __shared__ float Bsm[16][64];

    const int tid = threadIdx.x;
    const int arow = tid >> 2, akc = (tid & 3) * 4;
    const int bkr = tid >> 4, bcol = (tid & 15) * 4;
    const int ty = tid >> 4, tx = tid & 15;

    float acc[4][4];
#pragma unroll
    for (int i = 0; i < 4; ++i)
#pragma unroll
        for (int j = 0; j < 4; ++j) acc[i][j] = 0.f;

    for (int k0 = 0; k0 < CDIM; k0 += 16) {
        float4 a4 = *(const float4*)(A + (size_t)(m0 + arow) * CDIM + k0 + akc);
        Asm[akc + 0][arow] = a4.x; Asm[akc + 1][arow] = a4.y;
        Asm[akc + 2][arow] = a4.z; Asm[akc + 3][arow] = a4.w;
        *(float4*)&Bsm[bkr][bcol] = *(const float4*)(B + (size_t)(k0 + bkr) * CDIM + n0 + bcol);
        __syncthreads();
#pragma unroll
        for (int kk = 0; kk < 16; ++kk) {
            float a0 = Asm[kk][ty * 4 + 0], a1 = Asm[kk][ty * 4 + 1];
            float a2 = Asm[kk][ty * 4 + 2], a3 = Asm[kk][ty * 4 + 3];
            float4 b4 = *(const float4*)&Bsm[kk][tx * 4];
            acc[0][0] = fmaf(a0, b4.x, acc[0][0]); acc[0][1] = fmaf(a0, b4.y, acc[0][1]);
            acc[0][2] = fmaf(a0, b4.z, acc[0][2]); acc[0][3] = fmaf(a0, b4.w, acc[0][3]);
            acc[1][0] = fmaf(a1, b4.x, acc[1][0]); acc[1][1] = fmaf(a1, b4.y, acc[1][1]);
            acc[1][2] = fmaf(a1, b4.z, acc[1][2]); acc[1][3] = fmaf(a1, b4.w, acc[1][3]);
            acc[2][0] = fmaf(a2, b4.x, acc[2][0]); acc[2][1] = fmaf(a2, b4.y, acc[2][1]);
            acc[2][2] = fmaf(a2, b4.z, acc[2][2]); acc[2][3] = fmaf(a2, b4.w, acc[2][3]);
            acc[3][0] = fmaf(a3, b4.x, acc[3][0]); acc[3][1] = fmaf(a3, b4.y, acc[3][1]);
            acc[3][2] = fmaf(a3, b4.z, acc[3][2]); acc[3][3] = fmaf(a3, b4.w, acc[3][3]);
        }
        __syncthreads();
    }
#pragma unroll
    for (int i = 0; i < 4; ++i)
        *(float4*)&C[(size_t)(m0 + ty * 4 + i) * CDIM + n0 + tx * 4] =
            make_float4(acc[i][0], acc[i][1], acc[i][2], acc[i][3]);
}

// ---------------- kernel: inv row norms  (via diag of W R^T) ----------------
// grid: (2, BATCH)  block 384 (12 warps, warp-per-row)
__global__ void norms_kernel(const float* __restrict__ wq, const float* __restrict__ wk) {
    const int which = blockIdx.x;
    const int b = blockIdx.y;
    const float* R = (which ? g_Rk : g_Rq) + (size_t)b * CDIM * CDIM;
    const float* W = which ? wk : wq;
    float* inv = (which ? g_invk : g_invq) + b * CDIM;
    const int lane = threadIdx.x & 31;
    const int wd = threadIdx.x >> 5;
    for (int r = wd; r < CDIM; r += 12) {
        float s = 0.f;
        for (int j = lane; j < CDIM; j += 32)
            s = fmaf(R[(size_t)r * CDIM + j], W[(size_t)r * CDIM + j], s);
#pragma unroll
        for (int o = 16; o; o >>= 1) s += __shfl_xor_sync(0xffffffffu, s, o);
        if (lane == 0) inv[r] = 1.f / fmaxf(sqrtf(fmaxf(s, 0.f)), EPS);
    }
}

// ---------------- kernel: S_h = Rq(head rows) @ Wk(head rows)^T ----------------
// grid: 64 (b*8+h), block 256; K=384 in 6 chunks of 64, 3x3 micro
__global__ __launch_bounds__(256) void s_kernel(const float* __restrict__ wk) {
    const int bh = blockIdx.x;
    const int b = bh >> 3;
    const int h = bh & 7;
    const int tid = threadIdx.x;

    __shared__ float qs[CH][68];
    __shared__ float ks[CH][68];

    const int c0 = (tid >> 4) * 3;
    const int d0 = (tid & 15) * 3;

    float acc[3][3];
#pragma unroll
    for (int i = 0; i < 3; ++i)
#pragma unroll
        for (int j = 0; j < 3; ++j) acc[i][j] = 0.f;

    const float* Rq = g_Rq + (size_t)b * CDIM * CDIM + (size_t)(h * CH) * CDIM;
    const float* Wk = wk + (size_t)(h * CH) * CDIM;

    for (int ck = 0; ck < 6; ++ck) {
        const int koff = ck * 64;
#pragma unroll
        for (int t = 0; t < 3; ++t) {
            int idx = t * 256 + tid;
            int row = idx >> 4;
            int col = (idx & 15) * 4;
            *(float4*)&qs[row][col] = *(const float4*)(Rq + (size_t)row * CDIM + koff + col);
            *(float4*)&ks[row][col] = *(const float4*)(Wk + (size_t)row * CDIM + koff + col);
        }
        __syncthreads();
#pragma unroll 8
        for (int kk = 0; kk < 64; ++kk) {
            float q0 = qs[c0 + 0][kk], q1 = qs[c0 + 1][kk], q2 = qs[c0 + 2][kk];
            float k0 = ks[d0 + 0][kk], k1 = ks[d0 + 1][kk], k2 = ks[d0 + 2][kk];
            acc[0][0] = fmaf(q0, k0, acc[0][0]);
            acc[0][1] = fmaf(q0, k1, acc[0][1]);
            acc[0][2] = fmaf(q0, k2, acc[0][2]);
            acc[1][0] = fmaf(q1, k0, acc[1][0]);
            acc[1][1] = fmaf(q1, k1, acc[1][1]);
            acc[1][2] = fmaf(q1, k2, acc[1][2]);
            acc[2][0] = fmaf(q2, k0, acc[2][0]);
            acc[2][1] = fmaf(q2, k1, acc[2][1]);
            acc[2][2] = fmaf(q2, k2, acc[2][2]);
        }
        __syncthreads();
    }

    float* Sb = g_S + (size_t)bh * CH * CH;
#pragma unroll
    for (int i = 0; i < 3; ++i)
#pragma unroll
        for (int j = 0; j < 3; ++j)
            Sb[(c0 + i) * CH + (d0 + j)] = acc[i][j];
}

// ---------------- kernel: scale + softmax ----------------
__global__ void attn_softmax_kernel(const float* __restrict__ temperature) {
    const int bh = blockIdx.x;
    const int b = bh >> 3;
    const int h = bh & 7;
    const int c = threadIdx.x;
    if (c >= CH) return;

    const float t = temperature[h];
    const float sq = g_invq[b * CDIM + h * CH + c] * t;
    const float* Srow = g_S + (size_t)bh * CH * CH + c * CH;
    const float* ik = g_invk + b * CDIM + h * CH;

    float v[CH];
    float m = -1e30f;
#pragma unroll
    for (int d = 0; d < CH; ++d) {
        v[d] = Srow[d] * sq * ik[d];
        m = fmaxf(m, v[d]);
    }
    float sum = 0.f;
#pragma unroll
    for (int d = 0; d < CH; ++d) {
        v[d] = __expf(v[d] - m);
        sum += v[d];
    }
    float inv = 1.f / sum;
    float* Arow = g_A + (size_t)bh * CH * CH + c * CH;
#pragma unroll
    for (int d = 0; d < CH; ++d) Arow[d] = v[d] * inv;
}

// ---------------- kernel: Bs rows [h*48 .. h*48+48) = A_h @ Wv(head rows) ----------------
// grid: 64 (bh), block 384 (thread = output column)
__global__ __launch_bounds__(384) void bstack_kernel(const float* __restrict__ wv) {
    const int bh = blockIdx.x;
    const int b = bh >> 3;
    const int h = bh & 7;

    __shared__ float As[CH * CH];
    const float* Ah = g_A + (size_t)bh * CH * CH;
    for (int i = threadIdx.x; i < CH * CH; i += 384) As[i] = Ah[i];
    __syncthreads();

    const int c = threadIdx.x;
    float acc[CH];
#pragma unroll
    for (int i = 0; i < CH; ++i) acc[i] = 0.f;

    const float* wvp = wv + (size_t)(h * CH) * CDIM + c;
    for (int d = 0; d < CH; ++d) {
        float wvv = wvp[(size_t)d * CDIM];
#pragma unroll
        for (int cp = 0; cp < CH; ++cp) acc[cp] = fmaf(As[cp * CH + d], wvv, acc[cp]);
    }
    float* out = g_Bs + (size_t)b * CDIM * CDIM + (size_t)(h * CH) * CDIM + c;
#pragma unroll
    for (int cp = 0; cp < CH; ++cp) out[(size_t)cp * CDIM] = acc[cp];
}

// ---------------- kernel: out = M @ x  (big GEMM) ----------------
// grid: (HW/128, 3, BATCH) block 256
__global__ __launch_bounds__(256) void out_gemm(const float* __restrict__ x,
                                                float* __restrict__ out) {
    const int bn = blockIdx.x * 128;
    const int obase = blockIdx.y * 128;
    const int b = blockIdx.z;
    const int tid = threadIdx.x;

    const float* __restrict__ A = g_M + (size_t)b * CDIM * CDIM;

    __shared__ float As[8][128];
    __shared__ float Bs[8][128];

    const int arow = tid >> 1;
    const int acol = (tid & 1) * 4;
    const float* aptr = A + (size_t)(obase + arow) * CDIM + acol;

    const int brow = tid >> 5;
    const int bcol = (tid & 31) * 4;
    const float* bptr = x + ((size_t)b * CDIM + brow) * HW + bn + bcol;

    const int rowBase = (tid >> 4) * 8;
    const int colBase = (tid & 15) * 8;

    float acc[8][8];
#pragma unroll
    for (int i = 0; i < 8; ++i)
#pragma unroll
        for (int j = 0; j < 8; ++j) acc[i][j] = 0.f;

    for (int kt = 0; kt < CDIM / 8; ++kt) {
        float4 av = *(const float4*)(aptr + kt * 8);
        As[acol + 0][arow] = av.x;
        As[acol + 1][arow] = av.y;
        As[acol + 2][arow] = av.z;
        As[acol + 3][arow] = av.w;
        float4 bv = *(const float4*)(bptr + (size_t)kt * 8 * HW);
        *(float4*)&Bs[brow][bcol] = bv;
        __syncthreads();
#pragma unroll
        for (int kk = 0; kk < 8; ++kk) {
            float4 a0 = *(const float4*)&As[kk][rowBase];
            float4 a1 = *(const float4*)&As[kk][rowBase + 4];
            float4 b0 = *(const float4*)&Bs[kk][colBase];
            float4 b1 = *(const float4*)&Bs[kk][colBase + 4];
            float ar[8] = {a0.x, a0.y, a0.z, a0.w, a1.x, a1.y, a1.z, a1.w};
            float br[8] = {b0.x, b0.y, b0.z, b0.w, b1.x, b1.y, b1.z, b1.w};
#pragma unroll
            for (int i = 0; i < 8; ++i)
#pragma unroll
                for (int j = 0; j < 8; ++j) acc[i][j] = fmaf(ar[i], br[j], acc[i][j]);
        }
        __syncthreads();
    }

#pragma unroll
    for (int i = 0; i < 8; ++i) {
        int o = obase + rowBase + i;
        float* p = out + ((size_t)b * CDIM + o) * HW + bn + colBase;
        *(float4*)p       = make_float4(acc[i][0], acc[i][1], acc[i][2], acc[i][3]);
        *(float4*)(p + 4) = make_float4(acc[i][4], acc[i][5], acc[i][6], acc[i][7]);
    }
}

// ---------------- launcher ----------------
extern "C" void kernel_launch(void* const* d_in, const int* in_sizes, int n_in,
                              void* d_out, int out_size) {
    const float* x    = (const float*)d_in[0];
    const float* wq   = (const float*)d_in[1];
    const float* wk   = (const float*)d_in[2];
    const float* wv   = (const float*)d_in[3];
    const float* wo   = (const float*)d_in[4];
    const float* temp = (const float*)d_in[5];
    float* out = (float*)d_out;

    const size_t CC = (size_t)CDIM * CDIM;
    const int nG = (int)(((size_t)BATCH * CC + 255) / 256);

    zero_G_kernel<<<nG, 256>>>();
    syrk_kernel<<<dim3(6, 16, BATCH), 256>>>(x);
    mirror_G_kernel<<<nG, 256>>>();

    // Rq = Wq @ G,  Rk = Wk @ G  (G symmetric; scratch resolved device-side)
    small_gemm<<<dim3(36, BATCH), 256>>>(wq, 0);
    small_gemm<<<dim3(36, BATCH), 256>>>(wk, 1);

    norms_kernel<<<dim3(2, BATCH), 384>>>(wq, wk);
    s_kernel<<<BATCH * NHEAD, 256>>>(wk);
    attn_softmax_kernel<<<BATCH * NHEAD, 64>>>(temp);
    bstack_kernel<<<BATCH * NHEAD, 384>>>(wv);

    // M = wo @ Bs
    small_gemm<<<dim3(36, BATCH), 256>>>(wo, 2);

    out_gemm<<<dim3(HW / 128, 3, BATCH), 256>>>(x, out);
}

// round 5
// speedup vs baseline: 2.0824x; 1.0498x over previous
#include <cuda_runtime.h>
#include <cuda_bf16.h>
#include <math.h>

#define BATCH 8
#define CDIM 384
#define NHEAD 8
#define CH 48
#define HW 16384
#define EPS 1e-12f

// ---------------- packed f32x2 helpers (Blackwell FFMA2 path) ----------------
__device__ __forceinline__ unsigned long long dupf2(float x) {
    unsigned long long r;
    asm("mov.b64 %0, {%1, %1};" : "=l"(r) : "f"(x));
    return r;
}
__device__ __forceinline__ void ffma2(unsigned long long& acc,
                                      unsigned long long a, unsigned long long b) {
    asm("fma.rn.f32x2 %0, %1, %2, %0;" : "+l"(acc) : "l"(a), "l"(b));
}
__device__ __forceinline__ float lo_f(unsigned long long v) {
    return __uint_as_float((unsigned)(v & 0xffffffffull));
}
__device__ __forceinline__ float hi_f(unsigned long long v) {
    return __uint_as_float((unsigned)(v >> 32));
}

// ---------------- scratch ----------------
__device__ float g_G [(size_t)BATCH * CDIM * CDIM];   // x x^T per batch (symmetric)
__device__ float g_Rq[(size_t)BATCH * CDIM * CDIM];   // Wq @ G
__device__ float g_Rk[(size_t)BATCH * CDIM * CDIM];   // Wk @ G
__device__ float g_invq[BATCH * CDIM];
__device__ float g_invk[BATCH * CDIM];
__device__ float g_S [BATCH * NHEAD * CH * CH];
__device__ float g_A [BATCH * NHEAD * CH * CH];
__device__ float g_Bs[(size_t)BATCH * CDIM * CDIM];   // blockdiag(A) @ Wv
__device__ float g_M [(size_t)BATCH * CDIM * CDIM];   // wo @ g_Bs

// ---------------- kernel: zero G ----------------
__global__ void zero_G_kernel() {
    size_t i = (size_t)blockIdx.x * 256 + threadIdx.x;
    if (i < (size_t)BATCH * CDIM * CDIM) g_G[i] = 0.f;
}

// ---------------- kernel: G = x x^T  (upper tile-triangle, split-K atomics) ----------------
// grid: (6 tile-pairs, 16 k-splits, BATCH), block 256. 128x128 tile, BK=8, FFMA2 micro.
__global__ __launch_bounds__(256) void syrk_kernel(const float* __restrict__ x) {
    const int TI[6] = {0, 0, 0, 1, 1, 2};
    const int TJ[6] = {0, 1, 2, 1, 2, 2};
    const int ti = TI[blockIdx.x], tj = TJ[blockIdx.x];
    const int b = blockIdx.z;
    const int koff0 = blockIdx.y * 1024;
    const int tid = threadIdx.x;

    __shared__ float As[8][128];
    __shared__ float Bs[8][128];

    const int lrow = tid >> 1;
    const int lkc = (tid & 1) * 4;
    const float* aptr = x + ((size_t)b * CDIM + ti * 128 + lrow) * HW + koff0 + lkc;
    const float* bptr = x + ((size_t)b * CDIM + tj * 128 + lrow) * HW + koff0 + lkc;

    const int rowBase = (tid >> 4) * 8;
    const int colBase = (tid & 15) * 8;

    unsigned long long acc2[8][4];
#pragma unroll
    for (int i = 0; i < 8; ++i)
#pragma unroll
        for (int j = 0; j < 4; ++j) acc2[i][j] = 0ull;

    for (int it = 0; it < 128; ++it) {
        float4 av = *(const float4*)(aptr + it * 8);
        float4 bv = *(const float4*)(bptr + it * 8);
        As[lkc + 0][lrow] = av.x; As[lkc + 1][lrow] = av.y;
        As[lkc + 2][lrow] = av.z; As[lkc + 3][lrow] = av.w;
        Bs[lkc + 0][lrow] = bv.x; Bs[lkc + 1][lrow] = bv.y;
        Bs[lkc + 2][lrow] = bv.z; Bs[lkc + 3][lrow] = bv.w;
        __syncthreads();
#pragma unroll
        for (int kk = 0; kk < 8; ++kk) {
            float4 a0 = *(const float4*)&As[kk][rowBase];
            float4 a1 = *(const float4*)&As[kk][rowBase + 4];
            const unsigned long long* bp = (const unsigned long long*)&Bs[kk][colBase];
            unsigned long long b20 = bp[0], b21 = bp[1], b22 = bp[2], b23 = bp[3];
            float ar[8] = {a0.x, a0.y, a0.z, a0.w, a1.x, a1.y, a1.z, a1.w};
#pragma unroll
            for (int i = 0; i < 8; ++i) {
                unsigned long long a2 = dupf2(ar[i]);
                ffma2(acc2[i][0], a2, b20);
                ffma2(acc2[i][1], a2, b21);
                ffma2(acc2[i][2], a2, b22);
                ffma2(acc2[i][3], a2, b23);
            }
        }
        __syncthreads();
    }

    float* Gp = g_G + (size_t)b * CDIM * CDIM;
#pragma unroll
    for (int i = 0; i < 8; ++i) {
        float* row = Gp + (size_t)(ti * 128 + rowBase + i) * CDIM + tj * 128 + colBase;
#pragma unroll
        for (int j = 0; j < 4; ++j) {
            atomicAdd(row + 2 * j,     lo_f(acc2[i][j]));
            atomicAdd(row + 2 * j + 1, hi_f(acc2[i][j]));
        }
    }
}

// ---------------- kernel: mirror lower tile-triangle of G ----------------
__global__ void mirror_G_kernel() {
    size_t i = (size_t)blockIdx.x * 256 + threadIdx.x;
    if (i >= (size_t)BATCH * CDIM * CDIM) return;
    size_t bb = i / (CDIM * CDIM);
    int rc = (int)(i % (CDIM * CDIM));
    int r = rc / CDIM, c = rc % CDIM;
    if ((r >> 7) > (c >> 7))
        g_G[i] = g_G[bb * CDIM * CDIM + (size_t)c * CDIM + r];
}

// ---------------- kernel: small GEMM (FFMA2 micro) ----------------
// mode 0: C=g_Rq, B=g_G   (A = wq)
// mode 1: C=g_Rk, B=g_G   (A = wk)
// mode 2: C=g_M,  B=g_Bs  (A = wo)
__global__ __launch_bounds__(256) void small_gemm(const float* __restrict__ A, int mode)
{
    const int m0 = (blockIdx.x % 6) * 64;
    const int n0 = (blockIdx.x / 6) * 64;
    const size_t z = blockIdx.y;
    const size_t CC = (size_t)CDIM * CDIM;

    const float* __restrict__ B = ((mode == 2) ? g_Bs : g_G) + z * CC;
    float* __restrict__ C = ((mode == 0) ? g_Rq : (mode == 1) ? g_Rk : g_M) + z * CC;

    __shared__ float Asm[16][68];
    __shared__ float Bsm[16][64];

    const int tid = threadIdx.x;
    const int arow = tid >> 2, akc = (tid & 3) * 4;
    const int bkr = tid >> 4, bcol = (tid & 15) * 4;
    const int ty = tid >> 4, tx = tid & 15;

    unsigned long long acc2[4][2];
#pragma unroll
    for (int i = 0; i < 4; ++i) { acc2[i][0] = 0ull; acc2[i][1] = 0ull; }

    for (int k0 = 0; k0 < CDIM; k0 += 16) {
        float4 a4 = *(const float4*)(A + (size_t)(m0 + arow) * CDIM + k0 + akc);
        Asm[akc + 0][arow] = a4.x; Asm[akc + 1][arow] = a4.y;
        Asm[akc + 2][arow] = a4.z; Asm[akc + 3][arow] = a4.w;
        *(float4*)&Bsm[bkr][bcol] = *(const float4*)(B + (size_t)(k0 + bkr) * CDIM + n0 + bcol);
        __syncthreads();
#pragma unroll
        for (int kk = 0; kk < 16; ++kk) {
            const unsigned long long* bp = (const unsigned long long*)&Bsm[kk][tx * 4];
            unsigned long long b20 = bp[0], b21 = bp[1];
#pragma unroll
            for (int i = 0; i < 4; ++i) {
                unsigned long long a2 = dupf2(Asm[kk][ty * 4 + i]);
                ffma2(acc2[i][0], a2, b20);
                ffma2(acc2[i][1], a2, b21);
            }
        }
        __syncthreads();
    }
#pragma unroll
    for (int i = 0; i < 4; ++i) {
        unsigned long long* cp =
            (unsigned long long*)&C[(size_t)(m0 + ty * 4 + i) * CDIM + n0 + tx * 4];
        cp[0] = acc2[i][0];
        cp[1] = acc2[i][1];
    }
}

// ---------------- kernel: inv row norms ----------------
__global__ void norms_kernel(const float* __restrict__ wq, const float* __restrict__ wk) {
    const int which = blockIdx.x;
    const int b = blockIdx.y;
    const float* R = (which ? g_Rk : g_Rq) + (size_t)b * CDIM * CDIM;
    const float* W = which ? wk : wq;
    float* inv = (which ? g_invk : g_invq) + b * CDIM;
    const int lane = threadIdx.x & 31;
    const int wd = threadIdx.x >> 5;
    for (int r = wd; r < CDIM; r += 12) {
        float s = 0.f;
        for (int j = lane; j < CDIM; j += 32)
            s = fmaf(R[(size_t)r * CDIM + j], W[(size_t)r * CDIM + j], s);
#pragma unroll
        for (int o = 16; o; o >>= 1) s += __shfl_xor_sync(0xffffffffu, s, o);
        if (lane == 0) inv[r] = 1.f / fmaxf(sqrtf(fmaxf(s, 0.f)), EPS);
    }
}

// ---------------- kernel: S_h = Rq(head rows) @ Wk(head rows)^T ----------------
__global__ __launch_bounds__(256) void s_kernel(const float* __restrict__ wk) {
    const int bh = blockIdx.x;
    const int b = bh >> 3;
    const int h = bh & 7;
    const int tid = threadIdx.x;

    __shared__ float qs[CH][68];
    __shared__ float ks[CH][68];

    const int c0 = (tid >> 4) * 3;
    const int d0 = (tid & 15) * 3;

    float acc[3][3];
#pragma unroll
    for (int i = 0; i < 3; ++i)
#pragma unroll
        for (int j = 0; j < 3; ++j) acc[i][j] = 0.f;

    const float* Rq = g_Rq + (size_t)b * CDIM * CDIM + (size_t)(h * CH) * CDIM;
    const float* Wk = wk + (size_t)(h * CH) * CDIM;

    for (int ck = 0; ck < 6; ++ck) {
        const int koff = ck * 64;
#pragma unroll
        for (int t = 0; t < 3; ++t) {
            int idx = t * 256 + tid;
            int row = idx >> 4;
            int col = (idx & 15) * 4;
            *(float4*)&qs[row][col] = *(const float4*)(Rq + (size_t)row * CDIM + koff + col);
            *(float4*)&ks[row][col] = *(const float4*)(Wk + (size_t)row * CDIM + koff + col);
        }
        __syncthreads();
#pragma unroll 8
        for (int kk = 0; kk < 64; ++kk) {
            float q0 = qs[c0 + 0][kk], q1 = qs[c0 + 1][kk], q2 = qs[c0 + 2][kk];
            float k0 = ks[d0 + 0][kk], k1 = ks[d0 + 1][kk], k2 = ks[d0 + 2][kk];
            acc[0][0] = fmaf(q0, k0, acc[0][0]);
            acc[0][1] = fmaf(q0, k1, acc[0][1]);
            acc[0][2] = fmaf(q0, k2, acc[0][2]);
            acc[1][0] = fmaf(q1, k0, acc[1][0]);
            acc[1][1] = fmaf(q1, k1, acc[1][1]);
            acc[1][2] = fmaf(q1, k2, acc[1][2]);
            acc[2][0] = fmaf(q2, k0, acc[2][0]);
            acc[2][1] = fmaf(q2, k1, acc[2][1]);
            acc[2][2] = fmaf(q2, k2, acc[2][2]);
        }
        __syncthreads();
    }

    float* Sb = g_S + (size_t)bh * CH * CH;
#pragma unroll
    for (int i = 0; i < 3; ++i)
#pragma unroll
        for (int j = 0; j < 3; ++j)
            Sb[(c0 + i) * CH + (d0 + j)] = acc[i][j];
}

// ---------------- kernel: scale + softmax ----------------
__global__ void attn_softmax_kernel(const float* __restrict__ temperature) {
    const int bh = blockIdx.x;
    const int b = bh >> 3;
    const int h = bh & 7;
    const int c = threadIdx.x;
    if (c >= CH) return;

    const float t = temperature[h];
    const float sq = g_invq[b * CDIM + h * CH + c] * t;
    const float* Srow = g_S + (size_t)bh * CH * CH + c * CH;
    const float* ik = g_invk + b * CDIM + h * CH;

    float v[CH];
    float m = -1e30f;
#pragma unroll
    for (int d = 0; d < CH; ++d) {
        v[d] = Srow[d] * sq * ik[d];
        m = fmaxf(m, v[d]);
    }
    float sum = 0.f;
#pragma unroll
    for (int d = 0; d < CH; ++d) {
        v[d] = __expf(v[d] - m);
        sum += v[d];
    }
    float inv = 1.f / sum;
    float* Arow = g_A + (size_t)bh * CH * CH + c * CH;
#pragma unroll
    for (int d = 0; d < CH; ++d) Arow[d] = v[d] * inv;
}

// ---------------- kernel: Bs rows = A_h @ Wv(head rows) ----------------
__global__ __launch_bounds__(384) void bstack_kernel(const float* __restrict__ wv) {
    const int bh = blockIdx.x;
    const int b = bh >> 3;
    const int h = bh & 7;

    __shared__ float As[CH * CH];
    const float* Ah = g_A + (size_t)bh * CH * CH;
    for (int i = threadIdx.x; i < CH * CH; i += 384) As[i] = Ah[i];
    __syncthreads();

    const int c = threadIdx.x;
    float acc[CH];
#pragma unroll
    for (int i = 0; i < CH; ++i) acc[i] = 0.f;

    const float* wvp = wv + (size_t)(h * CH) * CDIM + c;
    for (int d = 0; d < CH; ++d) {
        float wvv = wvp[(size_t)d * CDIM];
#pragma unroll
        for (int cp = 0; cp < CH; ++cp) acc[cp] = fmaf(As[cp * CH + d], wvv, acc[cp]);
    }
    float* out = g_Bs + (size_t)b * CDIM * CDIM + (size_t)(h * CH) * CDIM + c;
#pragma unroll
    for (int cp = 0; cp < CH; ++cp) out[(size_t)cp * CDIM] = acc[cp];
}

// ---------------- kernel: out = M @ x  (big GEMM, FFMA2 micro) ----------------
// grid: (HW/128, 3, BATCH) block 256
__global__ __launch_bounds__(256) void out_gemm(const float* __restrict__ x,
                                                float* __restrict__ out) {
    const int bn = blockIdx.x * 128;
    const int obase = blockIdx.y * 128;
    const int b = blockIdx.z;
    const int tid = threadIdx.x;

    const float* __restrict__ A = g_M + (size_t)b * CDIM * CDIM;

    __shared__ float As[8][128];
    __shared__ float Bs[8][128];

    const int arow = tid >> 1;
    const int acol = (tid & 1) * 4;
    const float* aptr = A + (size_t)(obase + arow) * CDIM + acol;

    const int brow = tid >> 5;
    const int bcol = (tid & 31) * 4;
    const float* bptr = x + ((size_t)b * CDIM + brow) * HW + bn + bcol;

    const int rowBase = (tid >> 4) * 8;
    const int colBase = (tid & 15) * 8;

    unsigned long long acc2[8][4];
#pragma unroll
    for (int i = 0; i < 8; ++i)
#pragma unroll
        for (int j = 0; j < 4; ++j) acc2[i][j] = 0ull;

    for (int kt = 0; kt < CDIM / 8; ++kt) {
        float4 av = *(const float4*)(aptr + kt * 8);
        As[acol + 0][arow] = av.x;
        As[acol + 1][arow] = av.y;
        As[acol + 2][arow] = av.z;
        As[acol + 3][arow] = av.w;
        float4 bv = *(const float4*)(bptr + (size_t)kt * 8 * HW);
        *(float4*)&Bs[brow][bcol] = bv;
        __syncthreads();
#pragma unroll
        for (int kk = 0; kk < 8; ++kk) {
            float4 a0 = *(const float4*)&As[kk][rowBase];
            float4 a1 = *(const float4*)&As[kk][rowBase + 4];
            const unsigned long long* bp = (const unsigned long long*)&Bs[kk][colBase];
            unsigned long long b20 = bp[0], b21 = bp[1], b22 = bp[2], b23 = bp[3];
            float ar[8] = {a0.x, a0.y, a0.z, a0.w, a1.x, a1.y, a1.z, a1.w};
#pragma unroll
            for (int i = 0; i < 8; ++i) {
                unsigned long long a2 = dupf2(ar[i]);
                ffma2(acc2[i][0], a2, b20);
                ffma2(acc2[i][1], a2, b21);
                ffma2(acc2[i][2], a2, b22);
                ffma2(acc2[i][3], a2, b23);
            }
        }
        __syncthreads();
    }

#pragma unroll
    for (int i = 0; i < 8; ++i) {
        int o = obase + rowBase + i;
        unsigned long long* p =
            (unsigned long long*)(out + ((size_t)b * CDIM + o) * HW + bn + colBase);
        p[0] = acc2[i][0];
        p[1] = acc2[i][1];
        p[2] = acc2[i][2];
        p[3] = acc2[i][3];
    }
}

// ---------------- launcher ----------------
extern "C" void kernel_launch(void* const* d_in, const int* in_sizes, int n_in,
                              void* d_out, int out_size) {
    const float* x    = (const float*)d_in[0];
    const float* wq   = (const float*)d_in[1];
    const float* wk   = (const float*)d_in[2];
    const float* wv   = (const float*)d_in[3];
    const float* wo   = (const float*)d_in[4];
    const float* temp = (const float*)d_in[5];
    float* out = (float*)d_out;

    const size_t CC = (size_t)CDIM * CDIM;
    const int nG = (int)(((size_t)BATCH * CC + 255) / 256);

    zero_G_kernel<<<nG, 256>>>();
    syrk_kernel<<<dim3(6, 16, BATCH), 256>>>(x);
    mirror_G_kernel<<<nG, 256>>>();

    small_gemm<<<dim3(36, BATCH), 256>>>(wq, 0);
    small_gemm<<<dim3(36, BATCH), 256>>>(wk, 1);

    norms_kernel<<<dim3(2, BATCH), 384>>>(wq, wk);
    s_kernel<<<BATCH * NHEAD, 256>>>(wk);
    attn_softmax_kernel<<<BATCH * NHEAD, 64>>>(temp);
    bstack_kernel<<<BATCH * NHEAD, 384>>>(wv);

    small_gemm<<<dim3(36, BATCH), 256>>>(wo, 2);

    out_gemm<<<dim3(HW / 128, 3, BATCH), 256>>>(x, out);
}

// round 7
// speedup vs baseline: 4.4973x; 2.1597x over previous
#include <cuda_runtime.h>
#include <cuda_bf16.h>
#include <math.h>
#include <stdint.h>

#define BATCH 8
#define CDIM 384
#define NHEAD 8
#define CH 48
#define HW 16384
#define EPS 1e-12f

// ---------------- warp-MMA helpers (plain sm_80+ PTX; no 'a' features) ----------------
__device__ __forceinline__ uint32_t smem_u32(const void* p) {
    uint32_t a;
    asm("{ .reg .u64 t; cvta.to.shared.u64 t, %1; cvt.u32.u64 %0, t; }" : "=r"(a) : "l"(p));
    return a;
}
__device__ __forceinline__ void ldm_x4(uint32_t* r, uint32_t addr) {
    asm volatile("ldmatrix.sync.aligned.m8n8.x4.shared.b16 {%0,%1,%2,%3}, [%4];"
                 : "=r"(r[0]), "=r"(r[1]), "=r"(r[2]), "=r"(r[3]) : "r"(addr));
}
__device__ __forceinline__ void mma_bf16(float* d, const uint32_t* a, const uint32_t* b) {
    asm volatile(
        "mma.sync.aligned.m16n8k16.row.col.f32.bf16.bf16.f32 "
        "{%0,%1,%2,%3}, {%4,%5,%6,%7}, {%8,%9}, {%0,%1,%2,%3};"
        : "+f"(d[0]), "+f"(d[1]), "+f"(d[2]), "+f"(d[3])
        : "r"(a[0]), "r"(a[1]), "r"(a[2]), "r"(a[3]), "r"(b[0]), "r"(b[1]));
}

// ---------------- scratch ----------------
__device__ float g_G [(size_t)BATCH * CDIM * CDIM];
__device__ float g_Rq[(size_t)BATCH * CDIM * CDIM];
__device__ float g_Rk[(size_t)BATCH * CDIM * CDIM];
__device__ float g_invq[BATCH * CDIM];
__device__ float g_invk[BATCH * CDIM];
__device__ float g_S [BATCH * NHEAD * CH * CH];
__device__ float g_A [BATCH * NHEAD * CH * CH];
__device__ float g_Bs[(size_t)BATCH * CDIM * CDIM];
__device__ float g_M [(size_t)BATCH * CDIM * CDIM];

__device__ __nv_bfloat16 g_xhi [(size_t)BATCH * CDIM * HW];  // [b][c][n]
__device__ __nv_bfloat16 g_xlo [(size_t)BATCH * CDIM * HW];
__device__ __nv_bfloat16 g_xThi[(size_t)BATCH * HW * CDIM];  // [b][n][c]
__device__ __nv_bfloat16 g_xTlo[(size_t)BATCH * HW * CDIM];
__device__ __nv_bfloat16 g_Mhi [(size_t)BATCH * CDIM * CDIM];
__device__ __nv_bfloat16 g_Mlo [(size_t)BATCH * CDIM * CDIM];

// ---------------- convert x -> bf16 hi/lo + transposed copies ----------------
// grid (HW/32, CDIM/32, BATCH), block (32,8)
__global__ void convert_x_kernel(const float* __restrict__ x) {
    const int b = blockIdx.z;
    const int c0 = blockIdx.y * 32;
    const int n0 = blockIdx.x * 32;
    __shared__ float t[32][33];
    const int tx = threadIdx.x, ty = threadIdx.y;

#pragma unroll
    for (int k = 0; k < 4; ++k) {
        int c = c0 + ty + 8 * k;
        size_t o = ((size_t)b * CDIM + c) * HW + n0 + tx;
        float v = x[o];
        t[ty + 8 * k][tx] = v;
        __nv_bfloat16 h = __float2bfloat16(v);
        __nv_bfloat16 l = __float2bfloat16(v - __bfloat162float(h));
        g_xhi[o] = h;
        g_xlo[o] = l;
    }
    __syncthreads();
#pragma unroll
    for (int k = 0; k < 4; ++k) {
        int n = n0 + ty + 8 * k;
        float v = t[tx][ty + 8 * k];
        __nv_bfloat16 h = __float2bfloat16(v);
        __nv_bfloat16 l = __float2bfloat16(v - __bfloat162float(h));
        size_t o = ((size_t)b * HW + n) * CDIM + c0 + tx;
        g_xThi[o] = h;
        g_xTlo[o] = l;
    }
}

__global__ void convert_M_kernel() {
    size_t i = (size_t)blockIdx.x * 256 + threadIdx.x;
    if (i >= (size_t)BATCH * CDIM * CDIM) return;
    float v = g_M[i];
    __nv_bfloat16 h = __float2bfloat16(v);
    g_Mhi[i] = h;
    g_Mlo[i] = __float2bfloat16(v - __bfloat162float(h));
}

__global__ void zero_G_kernel() {
    size_t i = (size_t)blockIdx.x * 256 + threadIdx.x;
    if (i < (size_t)BATCH * CDIM * CDIM) g_G[i] = 0.f;
}

// ---------------- shared tile geometry for MMA kernels ----------------
// Each tile: 128 rows x 32 bf16 cols, row stride 40 bf16 (80 B) for conflict-free ldmatrix.
#define ROWB 80
#define TILE_BYTES (128 * ROWB)   // 10240
#define OFF_AH 0
#define OFF_AL (1 * TILE_BYTES)
#define OFF_BH (2 * TILE_BYTES)
#define OFF_BL (3 * TILE_BYTES)
#define SMEM_MMA (4 * TILE_BYTES) // 40960

// Load one 128x32 bf16 tile (2 uint4 per thread). srcRow = row stride in bf16 elems.
__device__ __forceinline__ void load_tile(char* sm, uint32_t off,
                                          const __nv_bfloat16* src, size_t srcStride,
                                          int k0, int tid) {
#pragma unroll
    for (int t = 0; t < 2; ++t) {
        int idx = t * 256 + tid;
        int r = idx >> 2, g = idx & 3;
        *(uint4*)(sm + off + r * ROWB + g * 16) =
            *(const uint4*)(src + (size_t)r * srcStride + k0 + g * 8);
    }
}

// Warp-level 64x32 3-term bf16 MMA over one 32-wide k chunk in smem.
__device__ __forceinline__ void mma_chunk(uint32_t sbase, int lane, int wm, int wn,
                                          float acc[4][4][4]) {
#pragma unroll
    for (int kk = 0; kk < 2; ++kk) {
        uint32_t a_hi[4][4], a_lo[4][4], b_hi[2][4], b_lo[2][4];
        const uint32_t arow = (uint32_t)(wm * 64 + (lane & 15));
        const uint32_t acol = ((lane >> 4) * 16) + kk * 32;
#pragma unroll
        for (int mi = 0; mi < 4; ++mi) {
            uint32_t off = (arow + mi * 16) * ROWB + acol;
            ldm_x4(a_hi[mi], sbase + OFF_AH + off);
            ldm_x4(a_lo[mi], sbase + OFF_AL + off);
        }
        const uint32_t brow = (uint32_t)(wn * 32 + ((lane >> 4) << 3) + (lane & 7));
        const uint32_t bcol = (((lane >> 3) & 1) * 16) + kk * 32;
#pragma unroll
        for (int nj = 0; nj < 2; ++nj) {
            uint32_t off = (brow + nj * 16) * ROWB + bcol;
            ldm_x4(b_hi[nj], sbase + OFF_BH + off);
            ldm_x4(b_lo[nj], sbase + OFF_BL + off);
        }
#pragma unroll
        for (int mi = 0; mi < 4; ++mi)
#pragma unroll
            for (int nj = 0; nj < 2; ++nj) {
                mma_bf16(acc[mi][nj * 2 + 0], a_hi[mi], &b_hi[nj][0]);
                mma_bf16(acc[mi][nj * 2 + 1], a_hi[mi], &b_hi[nj][2]);
                mma_bf16(acc[mi][nj * 2 + 0], a_hi[mi], &b_lo[nj][0]);
                mma_bf16(acc[mi][nj * 2 + 1], a_hi[mi], &b_lo[nj][2]);
                mma_bf16(acc[mi][nj * 2 + 0], a_lo[mi], &b_hi[nj][0]);
                mma_bf16(acc[mi][nj * 2 + 1], a_lo[mi], &b_hi[nj][2]);
            }
    }
}

// ---------------- syrk: G += x x^T (tensor cores, 6 tile-pairs, split-K) ----------------
// grid (6, 16, BATCH), 256 threads
__global__ __launch_bounds__(256) void syrk_mma() {
    __shared__ __align__(16) char sm[SMEM_MMA];
    const int tid = threadIdx.x, lane = tid & 31, wid = tid >> 5;
    const int wm = wid & 1, wn = wid >> 1;
    const int TI[6] = {0, 0, 0, 1, 1, 2};
    const int TJ[6] = {0, 1, 2, 1, 2, 2};
    const int ti = TI[blockIdx.x], tj = TJ[blockIdx.x];
    const int b = blockIdx.z;
    const int kb = blockIdx.y * 1024;

    const __nv_bfloat16* Ah = g_xhi + ((size_t)(b * CDIM + ti * 128)) * HW;
    const __nv_bfloat16* Al = g_xlo + ((size_t)(b * CDIM + ti * 128)) * HW;
    const __nv_bfloat16* Bh = g_xhi + ((size_t)(b * CDIM + tj * 128)) * HW;
    const __nv_bfloat16* Bl = g_xlo + ((size_t)(b * CDIM + tj * 128)) * HW;

    float acc[4][4][4];
#pragma unroll
    for (int i = 0; i < 4; ++i)
#pragma unroll
        for (int j = 0; j < 4; ++j)
#pragma unroll
            for (int k = 0; k < 4; ++k) acc[i][j][k] = 0.f;

    const uint32_t sbase = smem_u32(sm);
    for (int ch = 0; ch < 32; ++ch) {
        const int k0 = kb + ch * 32;
        __syncthreads();
        load_tile(sm, OFF_AH, Ah, HW, k0, tid);
        load_tile(sm, OFF_AL, Al, HW, k0, tid);
        load_tile(sm, OFF_BH, Bh, HW, k0, tid);
        load_tile(sm, OFF_BL, Bl, HW, k0, tid);
        __syncthreads();
        mma_chunk(sbase, lane, wm, wn, acc);
    }

    float* Gp = g_G + (size_t)b * CDIM * CDIM;
    const int r0 = ti * 128 + wm * 64;
    const int c0 = tj * 128 + wn * 32;
#pragma unroll
    for (int mi = 0; mi < 4; ++mi)
#pragma unroll
        for (int f = 0; f < 4; ++f) {
            int row = r0 + mi * 16 + (lane >> 2);
            int col = c0 + f * 8 + (lane & 3) * 2;
            atomicAdd(&Gp[(size_t)row * CDIM + col],           acc[mi][f][0]);
            atomicAdd(&Gp[(size_t)row * CDIM + col + 1],       acc[mi][f][1]);
            atomicAdd(&Gp[(size_t)(row + 8) * CDIM + col],     acc[mi][f][2]);
            atomicAdd(&Gp[(size_t)(row + 8) * CDIM + col + 1], acc[mi][f][3]);
        }
}

__global__ void mirror_G_kernel() {
    size_t i = (size_t)blockIdx.x * 256 + threadIdx.x;
    if (i >= (size_t)BATCH * CDIM * CDIM) return;
    size_t bb = i / (CDIM * CDIM);
    int rc = (int)(i % (CDIM * CDIM));
    int r = rc / CDIM, c = rc % CDIM;
    if ((r >> 7) > (c >> 7))
        g_G[i] = g_G[bb * CDIM * CDIM + (size_t)c * CDIM + r];
}

// ---------------- out = M @ x (tensor cores) ----------------
// grid (HW/128, 3, BATCH), 256 threads. A = M rows (o), B = xT rows (n), k = c.
__global__ __launch_bounds__(256) void out_mma(float* __restrict__ out) {
    __shared__ __align__(16) char sm[SMEM_MMA];
    const int tid = threadIdx.x, lane = tid & 31, wid = tid >> 5;
    const int wm = wid & 1, wn = wid >> 1;
    const int ntile = blockIdx.x;
    const int otile = blockIdx.y;
    const int b = blockIdx.z;

    const __nv_bfloat16* Ah = g_Mhi + (size_t)b * CDIM * CDIM + (size_t)(otile * 128) * CDIM;
    const __nv_bfloat16* Al = g_Mlo + (size_t)b * CDIM * CDIM + (size_t)(otile * 128) * CDIM;
    const __nv_bfloat16* Bh = g_xThi + ((size_t)b * HW + ntile * 128) * CDIM;
    const __nv_bfloat16* Bl = g_xTlo + ((size_t)b * HW + ntile * 128) * CDIM;

    float acc[4][4][4];
#pragma unroll
    for (int i = 0; i < 4; ++i)
#pragma unroll
        for (int j = 0; j < 4; ++j)
#pragma unroll
            for (int k = 0; k < 4; ++k) acc[i][j][k] = 0.f;

    const uint32_t sbase = smem_u32(sm);
    for (int ch = 0; ch < 12; ++ch) {
        const int k0 = ch * 32;
        __syncthreads();
        load_tile(sm, OFF_AH, Ah, CDIM, k0, tid);
        load_tile(sm, OFF_AL, Al, CDIM, k0, tid);
        load_tile(sm, OFF_BH, Bh, CDIM, k0, tid);
        load_tile(sm, OFF_BL, Bl, CDIM, k0, tid);
        __syncthreads();
        mma_chunk(sbase, lane, wm, wn, acc);
    }

    const int o0 = otile * 128 + wm * 64;
    const int n0 = ntile * 128 + wn * 32;
#pragma unroll
    for (int mi = 0; mi < 4; ++mi)
#pragma unroll
        for (int f = 0; f < 4; ++f) {
            int o = o0 + mi * 16 + (lane >> 2);
            int n = n0 + f * 8 + (lane & 3) * 2;
            float2 v0 = make_float2(acc[mi][f][0], acc[mi][f][1]);
            float2 v1 = make_float2(acc[mi][f][2], acc[mi][f][3]);
            *(float2*)&out[((size_t)b * CDIM + o) * HW + n] = v0;
            *(float2*)&out[((size_t)b * CDIM + o + 8) * HW + n] = v1;
        }
}

// ---------------- fp32 SIMT tail (unchanged) ----------------
__device__ __forceinline__ unsigned long long dupf2(float x) {
    unsigned long long r;
    asm("mov.b64 %0, {%1, %1};" : "=l"(r) : "f"(x));
    return r;
}
__device__ __forceinline__ void ffma2(unsigned long long& acc,
                                      unsigned long long a, unsigned long long b) {
    asm("fma.rn.f32x2 %0, %1, %2, %0;" : "+l"(acc) : "l"(a), "l"(b));
}

__global__ __launch_bounds__(256) void small_gemm(const float* __restrict__ A0,
                                                  const float* __restrict__ A1, int mode2)
{
    const int m0 = (blockIdx.x % 6) * 64;
    const int n0 = (blockIdx.x / 6) * 64;
    const size_t z = blockIdx.y;
    const size_t CC = (size_t)CDIM * CDIM;
    const int which = blockIdx.z;

    const float* __restrict__ A = mode2 ? A0 : (which ? A1 : A0);
    const float* __restrict__ B = (mode2 ? g_Bs : g_G) + z * CC;
    float* __restrict__ C = (mode2 ? g_M : (which ? g_Rk : g_Rq)) + z * CC;

    __shared__ float Asm[16][68];
    __shared__ float Bsm[16][64];

    const int tid = threadIdx.x;
    const int arow = tid >> 2, akc = (tid & 3) * 4;
    const int bkr = tid >> 4, bcol = (tid & 15) * 4;
    const int ty = tid >> 4, tx = tid & 15;

    unsigned long long acc2[4][2];
#pragma unroll
    for (int i = 0; i < 4; ++i) { acc2[i][0] = 0ull; acc2[i][1] = 0ull; }

    for (int k0 = 0; k0 < CDIM; k0 += 16) {
        float4 a4 = *(const float4*)(A + (size_t)(m0 + arow) * CDIM + k0 + akc);
        Asm[akc + 0][arow] = a4.x; Asm[akc + 1][arow] = a4.y;
        Asm[akc + 2][arow] = a4.z; Asm[akc + 3][arow] = a4.w;
        *(float4*)&Bsm[bkr][bcol] = *(const float4*)(B + (size_t)(k0 + bkr) * CDIM + n0 + bcol);
        __syncthreads();
#pragma unroll
        for (int kk = 0; kk < 16; ++kk) {
            const unsigned long long* bp = (const unsigned long long*)&Bsm[kk][tx * 4];
            unsigned long long b20 = bp[0], b21 = bp[1];
#pragma unroll
            for (int i = 0; i < 4; ++i) {
                unsigned long long a2 = dupf2(Asm[kk][ty * 4 + i]);
                ffma2(acc2[i][0], a2, b20);
                ffma2(acc2[i][1], a2, b21);
            }
        }
        __syncthreads();
    }
#pragma unroll
    for (int i = 0; i < 4; ++i) {
        unsigned long long* cp =
            (unsigned long long*)&C[(size_t)(m0 + ty * 4 + i) * CDIM + n0 + tx * 4];
        cp[0] = acc2[i][0];
        cp[1] = acc2[i][1];
    }
}

__global__ void norms_kernel(const float* __restrict__ wq, const float* __restrict__ wk) {
    const int which = blockIdx.x;
    const int b = blockIdx.y;
    const float* R = (which ? g_Rk : g_Rq) + (size_t)b * CDIM * CDIM;
    const float* W = which ? wk : wq;
    float* inv = (which ? g_invk : g_invq) + b * CDIM;
    const int lane = threadIdx.x & 31;
    const int wd = threadIdx.x >> 5;
    for (int r = wd; r < CDIM; r += 12) {
        float s = 0.f;
        for (int j = lane; j < CDIM; j += 32)
            s = fmaf(R[(size_t)r * CDIM + j], W[(size_t)r * CDIM + j], s);
#pragma unroll
        for (int o = 16; o; o >>= 1) s += __shfl_xor_sync(0xffffffffu, s, o);
        if (lane == 0) inv[r] = 1.f / fmaxf(sqrtf(fmaxf(s, 0.f)), EPS);
    }
}

__global__ __launch_bounds__(256) void s_kernel(const float* __restrict__ wk) {
    const int bh = blockIdx.x;
    const int b = bh >> 3;
    const int h = bh & 7;
    const int tid = threadIdx.x;

    __shared__ float qs[CH][68];
    __shared__ float ks[CH][68];

    const int c0 = (tid >> 4) * 3;
    const int d0 = (tid & 15) * 3;

    float acc[3][3];
#pragma unroll
    for (int i = 0; i < 3; ++i)
#pragma unroll
        for (int j = 0; j < 3; ++j) acc[i][j] = 0.f;

    const float* Rq = g_Rq + (size_t)b * CDIM * CDIM + (size_t)(h * CH) * CDIM;
    const float* Wk = wk + (size_t)(h * CH) * CDIM;

    for (int ck = 0; ck < 6; ++ck) {
        const int koff = ck * 64;
#pragma unroll
        for (int t = 0; t < 3; ++t) {
            int idx = t * 256 + tid;
            int row = idx >> 4;
            int col = (idx & 15) * 4;
            *(float4*)&qs[row][col] = *(const float4*)(Rq + (size_t)row * CDIM + koff + col);
            *(float4*)&ks[row][col] = *(const float4*)(Wk + (size_t)row * CDIM + koff + col);
        }
        __syncthreads();
#pragma unroll 8
        for (int kk = 0; kk < 64; ++kk) {
            float q0 = qs[c0 + 0][kk], q1 = qs[c0 + 1][kk], q2 = qs[c0 + 2][kk];
            float k0 = ks[d0 + 0][kk], k1 = ks[d0 + 1][kk], k2 = ks[d0 + 2][kk];
            acc[0][0] = fmaf(q0, k0, acc[0][0]);
            acc[0][1] = fmaf(q0, k1, acc[0][1]);
            acc[0][2] = fmaf(q0, k2, acc[0][2]);
            acc[1][0] = fmaf(q1, k0, acc[1][0]);
            acc[1][1] = fmaf(q1, k1, acc[1][1]);
            acc[1][2] = fmaf(q1, k2, acc[1][2]);
            acc[2][0] = fmaf(q2, k0, acc[2][0]);
            acc[2][1] = fmaf(q2, k1, acc[2][1]);
            acc[2][2] = fmaf(q2, k2, acc[2][2]);
        }
        __syncthreads();
    }

    float* Sb = g_S + (size_t)bh * CH * CH;
#pragma unroll
    for (int i = 0; i < 3; ++i)
#pragma unroll
        for (int j = 0; j < 3; ++j)
            Sb[(c0 + i) * CH + (d0 + j)] = acc[i][j];
}

__global__ void attn_softmax_kernel(const float* __restrict__ temperature) {
    const int bh = blockIdx.x;
    const int b = bh >> 3;
    const int h = bh & 7;
    const int c = threadIdx.x;
    if (c >= CH) return;

    const float t = temperature[h];
    const float sq = g_invq[b * CDIM + h * CH + c] * t;
    const float* Srow = g_S + (size_t)bh * CH * CH + c * CH;
    const float* ik = g_invk + b * CDIM + h * CH;

    float v[CH];
    float m = -1e30f;
#pragma unroll
    for (int d = 0; d < CH; ++d) {
        v[d] = Srow[d] * sq * ik[d];
        m = fmaxf(m, v[d]);
    }
    float sum = 0.f;
#pragma unroll
    for (int d = 0; d < CH; ++d) {
        v[d] = __expf(v[d] - m);
        sum += v[d];
    }
    float inv = 1.f / sum;
    float* Arow = g_A + (size_t)bh * CH * CH + c * CH;
#pragma unroll
    for (int d = 0; d < CH; ++d) Arow[d] = v[d] * inv;
}

__global__ __launch_bounds__(384) void bstack_kernel(const float* __restrict__ wv) {
    const int bh = blockIdx.x;
    const int b = bh >> 3;
    const int h = bh & 7;

    __shared__ float As[CH * CH];
    const float* Ahp = g_A + (size_t)bh * CH * CH;
    for (int i = threadIdx.x; i < CH * CH; i += 384) As[i] = Ahp[i];
    __syncthreads();

    const int c = threadIdx.x;
    float acc[CH];
#pragma unroll
    for (int i = 0; i < CH; ++i) acc[i] = 0.f;

    const float* wvp = wv + (size_t)(h * CH) * CDIM + c;
    for (int d = 0; d < CH; ++d) {
        float wvv = wvp[(size_t)d * CDIM];
#pragma unroll
        for (int cp = 0; cp < CH; ++cp) acc[cp] = fmaf(As[cp * CH + d], wvv, acc[cp]);
    }
    float* outp = g_Bs + (size_t)b * CDIM * CDIM + (size_t)(h * CH) * CDIM + c;
#pragma unroll
    for (int cp = 0; cp < CH; ++cp) outp[(size_t)cp * CDIM] = acc[cp];
}

// ---------------- launcher ----------------
extern "C" void kernel_launch(void* const* d_in, const int* in_sizes, int n_in,
                              void* d_out, int out_size) {
    const float* x    = (const float*)d_in[0];
    const float* wq   = (const float*)d_in[1];
    const float* wk   = (const float*)d_in[2];
    const float* wv   = (const float*)d_in[3];
    const float* wo   = (const float*)d_in[4];
    const float* temp = (const float*)d_in[5];
    float* out = (float*)d_out;

    const size_t CC = (size_t)CDIM * CDIM;
    const int nG = (int)(((size_t)BATCH * CC + 255) / 256);

    convert_x_kernel<<<dim3(HW / 32, CDIM / 32, BATCH), dim3(32, 8)>>>(x);
    zero_G_kernel<<<nG, 256>>>();
    syrk_mma<<<dim3(6, 16, BATCH), 256>>>();
    mirror_G_kernel<<<nG, 256>>>();

    small_gemm<<<dim3(36, BATCH, 2), 256>>>(wq, wk, 0);   // Rq, Rk

    norms_kernel<<<dim3(2, BATCH), 384>>>(wq, wk);
    s_kernel<<<BATCH * NHEAD, 256>>>(wk);
    attn_softmax_kernel<<<BATCH * NHEAD, 64>>>(temp);
    bstack_kernel<<<BATCH * NHEAD, 384>>>(wv);

    small_gemm<<<dim3(36, BATCH, 1), 256>>>(wo, wo, 1);   // M = wo @ Bs
    convert_M_kernel<<<nG, 256>>>();

    out_mma<<<dim3(HW / 128, 3, BATCH), 256>>>(out);
}

// round 8
// speedup vs baseline: 4.5781x; 1.0180x over previous
#include <cuda_runtime.h>
#include <cuda_bf16.h>
#include <math.h>
#include <stdint.h>

#define BATCH 8
#define CDIM 384
#define NHEAD 8
#define CH 48
#define HW 16384
#define EPS 1e-12f

// ---------------- warp-MMA + cp.async helpers (plain sm_80+ PTX) ----------------
__device__ __forceinline__ uint32_t smem_u32(const void* p) {
    uint32_t a;
    asm("{ .reg .u64 t; cvta.to.shared.u64 t, %1; cvt.u32.u64 %0, t; }" : "=r"(a) : "l"(p));
    return a;
}
__device__ __forceinline__ void ldm_x4(uint32_t* r, uint32_t addr) {
    asm volatile("ldmatrix.sync.aligned.m8n8.x4.shared.b16 {%0,%1,%2,%3}, [%4];"
                 : "=r"(r[0]), "=r"(r[1]), "=r"(r[2]), "=r"(r[3]) : "r"(addr));
}
__device__ __forceinline__ void mma_bf16(float* d, const uint32_t* a, const uint32_t* b) {
    asm volatile(
        "mma.sync.aligned.m16n8k16.row.col.f32.bf16.bf16.f32 "
        "{%0,%1,%2,%3}, {%4,%5,%6,%7}, {%8,%9}, {%0,%1,%2,%3};"
        : "+f"(d[0]), "+f"(d[1]), "+f"(d[2]), "+f"(d[3])
        : "r"(a[0]), "r"(a[1]), "r"(a[2]), "r"(a[3]), "r"(b[0]), "r"(b[1]));
}
__device__ __forceinline__ void cp_async16(uint32_t saddr, const void* gptr) {
    asm volatile("cp.async.cg.shared.global [%0], [%1], 16;" :: "r"(saddr), "l"(gptr));
}
#define CP_COMMIT() asm volatile("cp.async.commit_group;")
#define CP_WAIT(n)  asm volatile("cp.async.wait_group %0;" :: "n"(n))

// ---------------- scratch ----------------
__device__ float g_G [(size_t)BATCH * CDIM * CDIM];
__device__ float g_Rq[(size_t)BATCH * CDIM * CDIM];
__device__ float g_Rk[(size_t)BATCH * CDIM * CDIM];
__device__ float g_invq[BATCH * CDIM];
__device__ float g_invk[BATCH * CDIM];
__device__ float g_S [BATCH * NHEAD * CH * CH];
__device__ float g_A [BATCH * NHEAD * CH * CH];
__device__ float g_Bs[(size_t)BATCH * CDIM * CDIM];
__device__ float g_M [(size_t)BATCH * CDIM * CDIM];

__device__ __nv_bfloat16 g_xhi [(size_t)BATCH * CDIM * HW];  // [b][c][n]
__device__ __nv_bfloat16 g_xlo [(size_t)BATCH * CDIM * HW];
__device__ __nv_bfloat16 g_xThi[(size_t)BATCH * HW * CDIM];  // [b][n][c]
__device__ __nv_bfloat16 g_xTlo[(size_t)BATCH * HW * CDIM];
__device__ __nv_bfloat16 g_Mhi [(size_t)BATCH * CDIM * CDIM];
__device__ __nv_bfloat16 g_Mlo [(size_t)BATCH * CDIM * CDIM];

// ---------------- convert (flat, wide stores): x -> xhi/xlo ----------------
// grid 24576, block 256; 8 elems/thread; 16B stores.
__global__ void convert_plain(const float* __restrict__ x) {
    size_t i = ((size_t)blockIdx.x * 256 + threadIdx.x) * 8;
    float4 v0 = *(const float4*)(x + i);
    float4 v1 = *(const float4*)(x + i + 4);
    float v[8] = {v0.x, v0.y, v0.z, v0.w, v1.x, v1.y, v1.z, v1.w};
    __align__(16) __nv_bfloat16 hh[8], ll[8];
#pragma unroll
    for (int j = 0; j < 8; ++j) {
        __nv_bfloat16 h = __float2bfloat16(v[j]);
        hh[j] = h;
        ll[j] = __float2bfloat16(v[j] - __bfloat162float(h));
    }
    *(uint4*)(g_xhi + i) = *(const uint4*)hh;
    *(uint4*)(g_xlo + i) = *(const uint4*)ll;
}

// ---------------- convert transpose: x -> xThi/xTlo [b][n][c] ----------------
// grid (HW/32, CDIM/32, BATCH), block 128. Load coalesced along n; store 16B packs of 8 c.
__global__ void convert_T(const float* __restrict__ x) {
    const int b = blockIdx.z;
    const int c0 = blockIdx.y * 32;
    const int n0 = blockIdx.x * 32;
    __shared__ float t[32][33];
    const int tid = threadIdx.x;

    {
        const int ln = tid & 31;       // n local
        const int lc = tid >> 5;       // c group 0..3
#pragma unroll
        for (int k = 0; k < 8; ++k) {
            int c = lc * 8 + k;
            t[c][ln] = x[((size_t)b * CDIM + c0 + c) * HW + n0 + ln];
        }
    }
    __syncthreads();
    {
        const int lcg = tid & 3;       // c group 0..3
        const int ln = tid >> 2;       // n local 0..31
        __align__(16) __nv_bfloat16 hh[8], ll[8];
#pragma unroll
        for (int j = 0; j < 8; ++j) {
            float v = t[lcg * 8 + j][ln];
            __nv_bfloat16 h = __float2bfloat16(v);
            hh[j] = h;
            ll[j] = __float2bfloat16(v - __bfloat162float(h));
        }
        size_t o = ((size_t)b * HW + n0 + ln) * CDIM + c0 + lcg * 8;
        *(uint4*)(g_xThi + o) = *(const uint4*)hh;
        *(uint4*)(g_xTlo + o) = *(const uint4*)ll;
    }
}

__global__ void convert_M_kernel() {
    size_t i = (size_t)blockIdx.x * 256 + threadIdx.x;
    if (i >= (size_t)BATCH * CDIM * CDIM) return;
    float v = g_M[i];
    __nv_bfloat16 h = __float2bfloat16(v);
    g_Mhi[i] = h;
    g_Mlo[i] = __float2bfloat16(v - __bfloat162float(h));
}

__global__ void zero_G_kernel() {
    size_t i = (size_t)blockIdx.x * 256 + threadIdx.x;
    if (i < (size_t)BATCH * CDIM * CDIM) g_G[i] = 0.f;
}

// ---------------- MMA tile geometry ----------------
#define ROWB 80                     // 40 bf16 row stride (multiple of 16B)
#define TILE_BYTES (128 * ROWB)     // 10240
#define OFF_AH 0
#define OFF_AL (1 * TILE_BYTES)
#define OFF_BH (2 * TILE_BYTES)
#define OFF_BL (3 * TILE_BYTES)
#define STAGE_BYTES (4 * TILE_BYTES)   // 40960
#define PIPE_SMEM (2 * STAGE_BYTES)    // 81920

// Issue one stage of async loads (4 tiles of 128x32 bf16), 8 cp.async per thread.
__device__ __forceinline__ void issue_stage(uint32_t sdst,
    const __nv_bfloat16* Ah, const __nv_bfloat16* Al,
    const __nv_bfloat16* Bh, const __nv_bfloat16* Bl,
    size_t strideA, size_t strideB, int k0, int tid)
{
#pragma unroll
    for (int t = 0; t < 2; ++t) {
        int idx = t * 256 + tid;
        int r = idx >> 2, g = idx & 3;
        uint32_t so = (uint32_t)(r * ROWB + g * 16);
        size_t goA = (size_t)r * strideA + k0 + g * 8;
        size_t goB = (size_t)r * strideB + k0 + g * 8;
        cp_async16(sdst + OFF_AH + so, Ah + goA);
        cp_async16(sdst + OFF_AL + so, Al + goA);
        cp_async16(sdst + OFF_BH + so, Bh + goB);
        cp_async16(sdst + OFF_BL + so, Bl + goB);
    }
}

// Warp-level 64x32 3-term bf16 MMA over one 32-wide k chunk.
__device__ __forceinline__ void mma_chunk(uint32_t sbase, int lane, int wm, int wn,
                                          float acc[4][4][4]) {
#pragma unroll
    for (int kk = 0; kk < 2; ++kk) {
        uint32_t a_hi[4][4], a_lo[4][4], b_hi[2][4], b_lo[2][4];
        const uint32_t arow = (uint32_t)(wm * 64 + (lane & 15));
        const uint32_t acol = ((lane >> 4) * 16) + kk * 32;
#pragma unroll
        for (int mi = 0; mi < 4; ++mi) {
            uint32_t off = (arow + mi * 16) * ROWB + acol;
            ldm_x4(a_hi[mi], sbase + OFF_AH + off);
            ldm_x4(a_lo[mi], sbase + OFF_AL + off);
        }
        const uint32_t brow = (uint32_t)(wn * 32 + ((lane >> 4) << 3) + (lane & 7));
        const uint32_t bcol = (((lane >> 3) & 1) * 16) + kk * 32;
#pragma unroll
        for (int nj = 0; nj < 2; ++nj) {
            uint32_t off = (brow + nj * 16) * ROWB + bcol;
            ldm_x4(b_hi[nj], sbase + OFF_BH + off);
            ldm_x4(b_lo[nj], sbase + OFF_BL + off);
        }
#pragma unroll
        for (int mi = 0; mi < 4; ++mi)
#pragma unroll
            for (int nj = 0; nj < 2; ++nj) {
                mma_bf16(acc[mi][nj * 2 + 0], a_hi[mi], &b_hi[nj][0]);
                mma_bf16(acc[mi][nj * 2 + 1], a_hi[mi], &b_hi[nj][2]);
                mma_bf16(acc[mi][nj * 2 + 0], a_hi[mi], &b_lo[nj][0]);
                mma_bf16(acc[mi][nj * 2 + 1], a_hi[mi], &b_lo[nj][2]);
                mma_bf16(acc[mi][nj * 2 + 0], a_lo[mi], &b_hi[nj][0]);
                mma_bf16(acc[mi][nj * 2 + 1], a_lo[mi], &b_hi[nj][2]);
            }
    }
}

// ---------------- syrk: G += x x^T (pipelined) ----------------
// grid (6, 16, BATCH), 256 threads, 82KB dynamic smem
__global__ __launch_bounds__(256) void syrk_mma() {
    extern __shared__ __align__(16) char sm[];
    const int tid = threadIdx.x, lane = tid & 31, wid = tid >> 5;
    const int wm = wid & 1, wn = wid >> 1;
    const int TI[6] = {0, 0, 0, 1, 1, 2};
    const int TJ[6] = {0, 1, 2, 1, 2, 2};
    const int ti = TI[blockIdx.x], tj = TJ[blockIdx.x];
    const int b = blockIdx.z;
    const int kb = blockIdx.y * 1024;

    const __nv_bfloat16* Ah = g_xhi + ((size_t)(b * CDIM + ti * 128)) * HW;
    const __nv_bfloat16* Al = g_xlo + ((size_t)(b * CDIM + ti * 128)) * HW;
    const __nv_bfloat16* Bh = g_xhi + ((size_t)(b * CDIM + tj * 128)) * HW;
    const __nv_bfloat16* Bl = g_xlo + ((size_t)(b * CDIM + tj * 128)) * HW;

    float acc[4][4][4];
#pragma unroll
    for (int i = 0; i < 4; ++i)
#pragma unroll
        for (int j = 0; j < 4; ++j)
#pragma unroll
            for (int k = 0; k < 4; ++k) acc[i][j][k] = 0.f;

    const uint32_t sb = smem_u32(sm);
    issue_stage(sb, Ah, Al, Bh, Bl, HW, HW, kb, tid);
    CP_COMMIT();

    for (int ch = 0; ch < 32; ++ch) {
        if (ch < 31) {
            issue_stage(sb + ((ch + 1) & 1) * STAGE_BYTES, Ah, Al, Bh, Bl,
                        HW, HW, kb + (ch + 1) * 32, tid);
            CP_COMMIT();
            CP_WAIT(1);
        } else {
            CP_WAIT(0);
        }
        __syncthreads();
        mma_chunk(sb + (ch & 1) * STAGE_BYTES, lane, wm, wn, acc);
        __syncthreads();
    }

    float* Gp = g_G + (size_t)b * CDIM * CDIM;
    const int r0 = ti * 128 + wm * 64;
    const int c0 = tj * 128 + wn * 32;
#pragma unroll
    for (int mi = 0; mi < 4; ++mi)
#pragma unroll
        for (int f = 0; f < 4; ++f) {
            int row = r0 + mi * 16 + (lane >> 2);
            int col = c0 + f * 8 + (lane & 3) * 2;
            atomicAdd(&Gp[(size_t)row * CDIM + col],           acc[mi][f][0]);
            atomicAdd(&Gp[(size_t)row * CDIM + col + 1],       acc[mi][f][1]);
            atomicAdd(&Gp[(size_t)(row + 8) * CDIM + col],     acc[mi][f][2]);
            atomicAdd(&Gp[(size_t)(row + 8) * CDIM + col + 1], acc[mi][f][3]);
        }
}

__global__ void mirror_G_kernel() {
    size_t i = (size_t)blockIdx.x * 256 + threadIdx.x;
    if (i >= (size_t)BATCH * CDIM * CDIM) return;
    size_t bb = i / (CDIM * CDIM);
    int rc = (int)(i % (CDIM * CDIM));
    int r = rc / CDIM, c = rc % CDIM;
    if ((r >> 7) > (c >> 7))
        g_G[i] = g_G[bb * CDIM * CDIM + (size_t)c * CDIM + r];
}

// ---------------- out = M @ x (pipelined) ----------------
// grid (HW/128, 3, BATCH), 256 threads, 82KB dynamic smem
__global__ __launch_bounds__(256) void out_mma(float* __restrict__ out) {
    extern __shared__ __align__(16) char sm[];
    const int tid = threadIdx.x, lane = tid & 31, wid = tid >> 5;
    const int wm = wid & 1, wn = wid >> 1;
    const int ntile = blockIdx.x;
    const int otile = blockIdx.y;
    const int b = blockIdx.z;

    const __nv_bfloat16* Ah = g_Mhi + (size_t)b * CDIM * CDIM + (size_t)(otile * 128) * CDIM;
    const __nv_bfloat16* Al = g_Mlo + (size_t)b * CDIM * CDIM + (size_t)(otile * 128) * CDIM;
    const __nv_bfloat16* Bh = g_xThi + ((size_t)b * HW + ntile * 128) * CDIM;
    const __nv_bfloat16* Bl = g_xTlo + ((size_t)b * HW + ntile * 128) * CDIM;

    float acc[4][4][4];
#pragma unroll
    for (int i = 0; i < 4; ++i)
#pragma unroll
        for (int j = 0; j < 4; ++j)
#pragma unroll
            for (int k = 0; k < 4; ++k) acc[i][j][k] = 0.f;

    const uint32_t sb = smem_u32(sm);
    issue_stage(sb, Ah, Al, Bh, Bl, CDIM, CDIM, 0, tid);
    CP_COMMIT();

    for (int ch = 0; ch < 12; ++ch) {
        if (ch < 11) {
            issue_stage(sb + ((ch + 1) & 1) * STAGE_BYTES, Ah, Al, Bh, Bl,
                        CDIM, CDIM, (ch + 1) * 32, tid);
            CP_COMMIT();
            CP_WAIT(1);
        } else {
            CP_WAIT(0);
        }
        __syncthreads();
        mma_chunk(sb + (ch & 1) * STAGE_BYTES, lane, wm, wn, acc);
        __syncthreads();
    }

    const int o0 = otile * 128 + wm * 64;
    const int n0 = ntile * 128 + wn * 32;
#pragma unroll
    for (int mi = 0; mi < 4; ++mi)
#pragma unroll
        for (int f = 0; f < 4; ++f) {
            int o = o0 + mi * 16 + (lane >> 2);
            int n = n0 + f * 8 + (lane & 3) * 2;
            *(float2*)&out[((size_t)b * CDIM + o) * HW + n] =
                make_float2(acc[mi][f][0], acc[mi][f][1]);
            *(float2*)&out[((size_t)b * CDIM + o + 8) * HW + n] =
                make_float2(acc[mi][f][2], acc[mi][f][3]);
        }
}

// ---------------- fp32 SIMT tail (unchanged) ----------------
__device__ __forceinline__ unsigned long long dupf2(float x) {
    unsigned long long r;
    asm("mov.b64 %0, {%1, %1};" : "=l"(r) : "f"(x));
    return r;
}
__device__ __forceinline__ void ffma2(unsigned long long& acc,
                                      unsigned long long a, unsigned long long b) {
    asm("fma.rn.f32x2 %0, %1, %2, %0;" : "+l"(acc) : "l"(a), "l"(b));
}

__global__ __launch_bounds__(256) void small_gemm(const float* __restrict__ A0,
                                                  const float* __restrict__ A1, int mode2)
{
    const int m0 = (blockIdx.x % 6) * 64;
    const int n0 = (blockIdx.x / 6) * 64;
    const size_t z = blockIdx.y;
    const size_t CC = (size_t)CDIM * CDIM;
    const int which = blockIdx.z;

    const float* __restrict__ A = mode2 ? A0 : (which ? A1 : A0);
    const float* __restrict__ B = (mode2 ? g_Bs : g_G) + z * CC;
    float* __restrict__ C = (mode2 ? g_M : (which ? g_Rk : g_Rq)) + z * CC;

    __shared__ float Asm[16][68];
    __shared__ float Bsm[16][64];

    const int tid = threadIdx.x;
    const int arow = tid >> 2, akc = (tid & 3) * 4;
    const int bkr = tid >> 4, bcol = (tid & 15) * 4;
    const int ty = tid >> 4, tx = tid & 15;

    unsigned long long acc2[4][2];
#pragma unroll
    for (int i = 0; i < 4; ++i) { acc2[i][0] = 0ull; acc2[i][1] = 0ull; }

    for (int k0 = 0; k0 < CDIM; k0 += 16) {
        float4 a4 = *(const float4*)(A + (size_t)(m0 + arow) * CDIM + k0 + akc);
        Asm[akc + 0][arow] = a4.x; Asm[akc + 1][arow] = a4.y;
        Asm[akc + 2][arow] = a4.z; Asm[akc + 3][arow] = a4.w;
        *(float4*)&Bsm[bkr][bcol] = *(const float4*)(B + (size_t)(k0 + bkr) * CDIM + n0 + bcol);
        __syncthreads();
#pragma unroll
        for (int kk = 0; kk < 16; ++kk) {
            const unsigned long long* bp = (const unsigned long long*)&Bsm[kk][tx * 4];
            unsigned long long b20 = bp[0], b21 = bp[1];
#pragma unroll
            for (int i = 0; i < 4; ++i) {
                unsigned long long a2 = dupf2(Asm[kk][ty * 4 + i]);
                ffma2(acc2[i][0], a2, b20);
                ffma2(acc2[i][1], a2, b21);
            }
        }
        __syncthreads();
    }
#pragma unroll
    for (int i = 0; i < 4; ++i) {
        unsigned long long* cp =
            (unsigned long long*)&C[(size_t)(m0 + ty * 4 + i) * CDIM + n0 + tx * 4];
        cp[0] = acc2[i][0];
        cp[1] = acc2[i][1];
    }
}

__global__ void norms_kernel(const float* __restrict__ wq, const float* __restrict__ wk) {
    const int which = blockIdx.x;
    const int b = blockIdx.y;
    const float* R = (which ? g_Rk : g_Rq) + (size_t)b * CDIM * CDIM;
    const float* W = which ? wk : wq;
    float* inv = (which ? g_invk : g_invq) + b * CDIM;
    const int lane = threadIdx.x & 31;
    const int wd = threadIdx.x >> 5;
    for (int r = wd; r < CDIM; r += 12) {
        float s = 0.f;
        for (int j = lane; j < CDIM; j += 32)
            s = fmaf(R[(size_t)r * CDIM + j], W[(size_t)r * CDIM + j], s);
#pragma unroll
        for (int o = 16; o; o >>= 1) s += __shfl_xor_sync(0xffffffffu, s, o);
        if (lane == 0) inv[r] = 1.f / fmaxf(sqrtf(fmaxf(s, 0.f)), EPS);
    }
}

__global__ __launch_bounds__(256) void s_kernel(const float* __restrict__ wk) {
    const int bh = blockIdx.x;
    const int b = bh >> 3;
    const int h = bh & 7;
    const int tid = threadIdx.x;

    __shared__ float qs[CH][68];
    __shared__ float ks[CH][68];

    const int c0 = (tid >> 4) * 3;
    const int d0 = (tid & 15) * 3;

    float acc[3][3];
#pragma unroll
    for (int i = 0; i < 3; ++i)
#pragma unroll
        for (int j = 0; j < 3; ++j) acc[i][j] = 0.f;

    const float* Rq = g_Rq + (size_t)b * CDIM * CDIM + (size_t)(h * CH) * CDIM;
    const float* Wk = wk + (size_t)(h * CH) * CDIM;

    for (int ck = 0; ck < 6; ++ck) {
        const int koff = ck * 64;
#pragma unroll
        for (int t = 0; t < 3; ++t) {
            int idx = t * 256 + tid;
            int row = idx >> 4;
            int col = (idx & 15) * 4;
            *(float4*)&qs[row][col] = *(const float4*)(Rq + (size_t)row * CDIM + koff + col);
            *(float4*)&ks[row][col] = *(const float4*)(Wk + (size_t)row * CDIM + koff + col);
        }
        __syncthreads();
#pragma unroll 8
        for (int kk = 0; kk < 64; ++kk) {
            float q0 = qs[c0 + 0][kk], q1 = qs[c0 + 1][kk], q2 = qs[c0 + 2][kk];
            float k0 = ks[d0 + 0][kk], k1 = ks[d0 + 1][kk], k2 = ks[d0 + 2][kk];
            acc[0][0] = fmaf(q0, k0, acc[0][0]);
            acc[0][1] = fmaf(q0, k1, acc[0][1]);
            acc[0][2] = fmaf(q0, k2, acc[0][2]);
            acc[1][0] = fmaf(q1, k0, acc[1][0]);
            acc[1][1] = fmaf(q1, k1, acc[1][1]);
            acc[1][2] = fmaf(q1, k2, acc[1][2]);
            acc[2][0] = fmaf(q2, k0, acc[2][0]);
            acc[2][1] = fmaf(q2, k1, acc[2][1]);
            acc[2][2] = fmaf(q2, k2, acc[2][2]);
        }
        __syncthreads();
    }

    float* Sb = g_S + (size_t)bh * CH * CH;
#pragma unroll
    for (int i = 0; i < 3; ++i)
#pragma unroll
        for (int j = 0; j < 3; ++j)
            Sb[(c0 + i) * CH + (d0 + j)] = acc[i][j];
}

__global__ void attn_softmax_kernel(const float* __restrict__ temperature) {
    const int bh = blockIdx.x;
    const int b = bh >> 3;
    const int h = bh & 7;
    const int c = threadIdx.x;
    if (c >= CH) return;

    const float t = temperature[h];
    const float sq = g_invq[b * CDIM + h * CH + c] * t;
    const float* Srow = g_S + (size_t)bh * CH * CH + c * CH;
    const float* ik = g_invk + b * CDIM + h * CH;

    float v[CH];
    float m = -1e30f;
#pragma unroll
    for (int d = 0; d < CH; ++d) {
        v[d] = Srow[d] * sq * ik[d];
        m = fmaxf(m, v[d]);
    }
    float sum = 0.f;
#pragma unroll
    for (int d = 0; d < CH; ++d) {
        v[d] = __expf(v[d] - m);
        sum += v[d];
    }
    float inv = 1.f / sum;
    float* Arow = g_A + (size_t)bh * CH * CH + c * CH;
#pragma unroll
    for (int d = 0; d < CH; ++d) Arow[d] = v[d] * inv;
}

__global__ __launch_bounds__(384) void bstack_kernel(const float* __restrict__ wv) {
    const int bh = blockIdx.x;
    const int b = bh >> 3;
    const int h = bh & 7;

    __shared__ float As[CH * CH];
    const float* Ahp = g_A + (size_t)bh * CH * CH;
    for (int i = threadIdx.x; i < CH * CH; i += 384) As[i] = Ahp[i];
    __syncthreads();

    const int c = threadIdx.x;
    float acc[CH];
#pragma unroll
    for (int i = 0; i < CH; ++i) acc[i] = 0.f;

    const float* wvp = wv + (size_t)(h * CH) * CDIM + c;
    for (int d = 0; d < CH; ++d) {
        float wvv = wvp[(size_t)d * CDIM];
#pragma unroll
        for (int cp = 0; cp < CH; ++cp) acc[cp] = fmaf(As[cp * CH + d], wvv, acc[cp]);
    }
    float* outp = g_Bs + (size_t)b * CDIM * CDIM + (size_t)(h * CH) * CDIM + c;
#pragma unroll
    for (int cp = 0; cp < CH; ++cp) outp[(size_t)cp * CDIM] = acc[cp];
}

// ---------------- launcher ----------------
extern "C" void kernel_launch(void* const* d_in, const int* in_sizes, int n_in,
                              void* d_out, int out_size) {
    const float* x    = (const float*)d_in[0];
    const float* wq   = (const float*)d_in[1];
    const float* wk   = (const float*)d_in[2];
    const float* wv   = (const float*)d_in[3];
    const float* wo   = (const float*)d_in[4];
    const float* temp = (const float*)d_in[5];
    float* out = (float*)d_out;

    cudaFuncSetAttribute(syrk_mma, cudaFuncAttributeMaxDynamicSharedMemorySize, PIPE_SMEM);
    cudaFuncSetAttribute(out_mma, cudaFuncAttributeMaxDynamicSharedMemorySize, PIPE_SMEM);

    const size_t CC = (size_t)CDIM * CDIM;
    const int nG = (int)(((size_t)BATCH * CC + 255) / 256);

    convert_plain<<<24576, 256>>>(x);
    convert_T<<<dim3(HW / 32, CDIM / 32, BATCH), 128>>>(x);
    zero_G_kernel<<<nG, 256>>>();
    syrk_mma<<<dim3(6, 16, BATCH), 256, PIPE_SMEM>>>();
    mirror_G_kernel<<<nG, 256>>>();

    small_gemm<<<dim3(36, BATCH, 2), 256>>>(wq, wk, 0);   // Rq, Rk

    norms_kernel<<<dim3(2, BATCH), 384>>>(wq, wk);
    s_kernel<<<BATCH * NHEAD, 256>>>(wk);
    attn_softmax_kernel<<<BATCH * NHEAD, 64>>>(temp);
    bstack_kernel<<<BATCH * NHEAD, 384>>>(wv);

    small_gemm<<<dim3(36, BATCH, 1), 256>>>(wo, wo, 1);   // M = wo @ Bs
    convert_M_kernel<<<nG, 256>>>();

    out_mma<<<dim3(HW / 128, 3, BATCH), 256, PIPE_SMEM>>>(out);
}

// round 9
// speedup vs baseline: 4.7529x; 1.0382x over previous
#include <cuda_runtime.h>
#include <cuda_bf16.h>
#include <math.h>
#include <stdint.h>

#define BATCH 8
#define CDIM 384
#define NHEAD 8
#define CH 48
#define HW 16384
#define EPS 1e-12f

// ---------------- warp-MMA + cp.async helpers (plain sm_80+ PTX) ----------------
__device__ __forceinline__ uint32_t smem_u32(const void* p) {
    uint32_t a;
    asm("{ .reg .u64 t; cvta.to.shared.u64 t, %1; cvt.u32.u64 %0, t; }" : "=r"(a) : "l"(p));
    return a;
}
__device__ __forceinline__ void ldm_x4(uint32_t* r, uint32_t addr) {
    asm volatile("ldmatrix.sync.aligned.m8n8.x4.shared.b16 {%0,%1,%2,%3}, [%4];"
                 : "=r"(r[0]), "=r"(r[1]), "=r"(r[2]), "=r"(r[3]) : "r"(addr));
}
__device__ __forceinline__ void mma_bf16(float* d, const uint32_t* a, const uint32_t* b) {
    asm volatile(
        "mma.sync.aligned.m16n8k16.row.col.f32.bf16.bf16.f32 "
        "{%0,%1,%2,%3}, {%4,%5,%6,%7}, {%8,%9}, {%0,%1,%2,%3};"
        : "+f"(d[0]), "+f"(d[1]), "+f"(d[2]), "+f"(d[3])
        : "r"(a[0]), "r"(a[1]), "r"(a[2]), "r"(a[3]), "r"(b[0]), "r"(b[1]));
}
__device__ __forceinline__ void cp_async16(uint32_t saddr, const void* gptr) {
    asm volatile("cp.async.cg.shared.global [%0], [%1], 16;" :: "r"(saddr), "l"(gptr));
}
#define CP_COMMIT() asm volatile("cp.async.commit_group;")
#define CP_WAIT0()  asm volatile("cp.async.wait_group 0;")

// ---------------- scratch ----------------
__device__ float g_G [(size_t)BATCH * CDIM * CDIM];
__device__ float g_Rq[(size_t)BATCH * CDIM * CDIM];
__device__ float g_Rk[(size_t)BATCH * CDIM * CDIM];
__device__ float g_invq[BATCH * CDIM];
__device__ float g_invk[BATCH * CDIM];
__device__ float g_S [BATCH * NHEAD * CH * CH];
__device__ float g_A [BATCH * NHEAD * CH * CH];
__device__ float g_Bs[(size_t)BATCH * CDIM * CDIM];

__device__ __nv_bfloat16 g_xhi [(size_t)BATCH * CDIM * HW];  // [b][c][n]
__device__ __nv_bfloat16 g_xlo [(size_t)BATCH * CDIM * HW];
__device__ __nv_bfloat16 g_xThi[(size_t)BATCH * HW * CDIM];  // [b][n][c]
__device__ __nv_bfloat16 g_xTlo[(size_t)BATCH * HW * CDIM];
__device__ __nv_bfloat16 g_Mhi [(size_t)BATCH * CDIM * CDIM];
__device__ __nv_bfloat16 g_Mlo [(size_t)BATCH * CDIM * CDIM];

// ---------------- fused convert: x -> {xhi,xlo} and {xThi,xTlo} in one pass ----------------
// grid (HW/32, CDIM/32, BATCH), block 128. One read of x via smem tile.
__global__ void convert_x2(const float* __restrict__ x) {
    const int b = blockIdx.z;
    const int c0 = blockIdx.y * 32;
    const int n0 = blockIdx.x * 32;
    __shared__ float t[32][33];
    const int tid = threadIdx.x;

    {   // coalesced load of 32c x 32n tile
        const int ln = tid & 31;
        const int lc = tid >> 5;   // 0..3
#pragma unroll
        for (int k = 0; k < 8; ++k) {
            int c = lc * 8 + k;
            t[c][ln] = x[((size_t)b * CDIM + c0 + c) * HW + n0 + ln];
        }
    }
    __syncthreads();
    {   // plain layout: pack 8 n per thread for one c
        const int c = tid >> 2;    // 0..31
        const int ng = tid & 3;    // 0..3
        __align__(16) __nv_bfloat16 hh[8], ll[8];
#pragma unroll
        for (int j = 0; j < 8; ++j) {
            float v = t[c][ng * 8 + j];
            __nv_bfloat16 h = __float2bfloat16(v);
            hh[j] = h;
            ll[j] = __float2bfloat16(v - __bfloat162float(h));
        }
        size_t o = ((size_t)b * CDIM + c0 + c) * HW + n0 + ng * 8;
        *(uint4*)(g_xhi + o) = *(const uint4*)hh;
        *(uint4*)(g_xlo + o) = *(const uint4*)ll;
    }
    {   // transposed layout: pack 8 c per thread for one n
        const int lcg = tid & 3;   // 0..3
        const int ln = tid >> 2;   // 0..31
        __align__(16) __nv_bfloat16 hh[8], ll[8];
#pragma unroll
        for (int j = 0; j < 8; ++j) {
            float v = t[lcg * 8 + j][ln];
            __nv_bfloat16 h = __float2bfloat16(v);
            hh[j] = h;
            ll[j] = __float2bfloat16(v - __bfloat162float(h));
        }
        size_t o = ((size_t)b * HW + n0 + ln) * CDIM + c0 + lcg * 8;
        *(uint4*)(g_xThi + o) = *(const uint4*)hh;
        *(uint4*)(g_xTlo + o) = *(const uint4*)ll;
    }
}

__global__ void zero_G_kernel() {
    size_t i = (size_t)blockIdx.x * 256 + threadIdx.x;
    if (i < (size_t)BATCH * CDIM * CDIM) g_G[i] = 0.f;
}

// ---------------- MMA tile geometry ----------------
#define ROWB 80
#define TILE_BYTES (128 * ROWB)
#define OFF_AH 0
#define OFF_AL (1 * TILE_BYTES)
#define OFF_BH (2 * TILE_BYTES)
#define OFF_BL (3 * TILE_BYTES)
#define STAGE_BYTES (4 * TILE_BYTES)   // 40960
#define PIPE_SMEM (2 * STAGE_BYTES)    // 81920

__device__ __forceinline__ void issue_stage(uint32_t sdst,
    const __nv_bfloat16* Ah, const __nv_bfloat16* Al,
    const __nv_bfloat16* Bh, const __nv_bfloat16* Bl,
    size_t strideA, size_t strideB, int k0, int tid)
{
#pragma unroll
    for (int t = 0; t < 2; ++t) {
        int idx = t * 256 + tid;
        int r = idx >> 2, g = idx & 3;
        uint32_t so = (uint32_t)(r * ROWB + g * 16);
        size_t goA = (size_t)r * strideA + k0 + g * 8;
        size_t goB = (size_t)r * strideB + k0 + g * 8;
        cp_async16(sdst + OFF_AH + so, Ah + goA);
        cp_async16(sdst + OFF_AL + so, Al + goA);
        cp_async16(sdst + OFF_BH + so, Bh + goB);
        cp_async16(sdst + OFF_BL + so, Bl + goB);
    }
}

__device__ __forceinline__ void mma_chunk(uint32_t sbase, int lane, int wm, int wn,
                                          float acc[4][4][4]) {
#pragma unroll
    for (int kk = 0; kk < 2; ++kk) {
        uint32_t a_hi[4][4], a_lo[4][4], b_hi[2][4], b_lo[2][4];
        const uint32_t arow = (uint32_t)(wm * 64 + (lane & 15));
        const uint32_t acol = ((lane >> 4) * 16) + kk * 32;
#pragma unroll
        for (int mi = 0; mi < 4; ++mi) {
            uint32_t off = (arow + mi * 16) * ROWB + acol;
            ldm_x4(a_hi[mi], sbase + OFF_AH + off);
            ldm_x4(a_lo[mi], sbase + OFF_AL + off);
        }
        const uint32_t brow = (uint32_t)(wn * 32 + ((lane >> 4) << 3) + (lane & 7));
        const uint32_t bcol = (((lane >> 3) & 1) * 16) + kk * 32;
#pragma unroll
        for (int nj = 0; nj < 2; ++nj) {
            uint32_t off = (brow + nj * 16) * ROWB + bcol;
            ldm_x4(b_hi[nj], sbase + OFF_BH + off);
            ldm_x4(b_lo[nj], sbase + OFF_BL + off);
        }
#pragma unroll
        for (int mi = 0; mi < 4; ++mi)
#pragma unroll
            for (int nj = 0; nj < 2; ++nj) {
                mma_bf16(acc[mi][nj * 2 + 0], a_hi[mi], &b_hi[nj][0]);
                mma_bf16(acc[mi][nj * 2 + 1], a_hi[mi], &b_hi[nj][2]);
                mma_bf16(acc[mi][nj * 2 + 0], a_hi[mi], &b_lo[nj][0]);
                mma_bf16(acc[mi][nj * 2 + 1], a_hi[mi], &b_lo[nj][2]);
                mma_bf16(acc[mi][nj * 2 + 0], a_lo[mi], &b_hi[nj][0]);
                mma_bf16(acc[mi][nj * 2 + 1], a_lo[mi], &b_hi[nj][2]);
            }
    }
}

// ---------------- syrk: G += x x^T (single-barrier pipeline) ----------------
// grid (6, 16, BATCH), 256 threads, 80KB dynamic smem
__global__ __launch_bounds__(256) void syrk_mma() {
    extern __shared__ __align__(16) char sm[];
    const int tid = threadIdx.x, lane = tid & 31, wid = tid >> 5;
    const int wm = wid & 1, wn = wid >> 1;
    const int TI[6] = {0, 0, 0, 1, 1, 2};
    const int TJ[6] = {0, 1, 2, 1, 2, 2};
    const int ti = TI[blockIdx.x], tj = TJ[blockIdx.x];
    const int b = blockIdx.z;
    const int kb = blockIdx.y * 1024;

    const __nv_bfloat16* Ah = g_xhi + ((size_t)(b * CDIM + ti * 128)) * HW;
    const __nv_bfloat16* Al = g_xlo + ((size_t)(b * CDIM + ti * 128)) * HW;
    const __nv_bfloat16* Bh = g_xhi + ((size_t)(b * CDIM + tj * 128)) * HW;
    const __nv_bfloat16* Bl = g_xlo + ((size_t)(b * CDIM + tj * 128)) * HW;

    float acc[4][4][4];
#pragma unroll
    for (int i = 0; i < 4; ++i)
#pragma unroll
        for (int j = 0; j < 4; ++j)
#pragma unroll
            for (int k = 0; k < 4; ++k) acc[i][j][k] = 0.f;

    const uint32_t sb = smem_u32(sm);
    issue_stage(sb, Ah, Al, Bh, Bl, HW, HW, kb, tid);
    CP_COMMIT();

    for (int ch = 0; ch < 32; ++ch) {
        CP_WAIT0();
        __syncthreads();
        if (ch < 31) {
            // safe: all warps passed the barrier, so none still reads slot (ch+1)&1
            issue_stage(sb + ((ch + 1) & 1) * STAGE_BYTES, Ah, Al, Bh, Bl,
                        HW, HW, kb + (ch + 1) * 32, tid);
            CP_COMMIT();
        }
        mma_chunk(sb + (ch & 1) * STAGE_BYTES, lane, wm, wn, acc);
    }

    float* Gp = g_G + (size_t)b * CDIM * CDIM;
    const int r0 = ti * 128 + wm * 64;
    const int c0 = tj * 128 + wn * 32;
#pragma unroll
    for (int mi = 0; mi < 4; ++mi)
#pragma unroll
        for (int f = 0; f < 4; ++f) {
            int row = r0 + mi * 16 + (lane >> 2);
            int col = c0 + f * 8 + (lane & 3) * 2;
            atomicAdd(&Gp[(size_t)row * CDIM + col],           acc[mi][f][0]);
            atomicAdd(&Gp[(size_t)row * CDIM + col + 1],       acc[mi][f][1]);
            atomicAdd(&Gp[(size_t)(row + 8) * CDIM + col],     acc[mi][f][2]);
            atomicAdd(&Gp[(size_t)(row + 8) * CDIM + col + 1], acc[mi][f][3]);
        }
}

__global__ void mirror_G_kernel() {
    size_t i = (size_t)blockIdx.x * 256 + threadIdx.x;
    if (i >= (size_t)BATCH * CDIM * CDIM) return;
    size_t bb = i / (CDIM * CDIM);
    int rc = (int)(i % (CDIM * CDIM));
    int r = rc / CDIM, c = rc % CDIM;
    if ((r >> 7) > (c >> 7))
        g_G[i] = g_G[bb * CDIM * CDIM + (size_t)c * CDIM + r];
}

// ---------------- out = M @ x (single-barrier pipeline) ----------------
// grid (HW/128, 3, BATCH), 256 threads, 80KB dynamic smem
__global__ __launch_bounds__(256) void out_mma(float* __restrict__ out) {
    extern __shared__ __align__(16) char sm[];
    const int tid = threadIdx.x, lane = tid & 31, wid = tid >> 5;
    const int wm = wid & 1, wn = wid >> 1;
    const int ntile = blockIdx.x;
    const int otile = blockIdx.y;
    const int b = blockIdx.z;

    const __nv_bfloat16* Ah = g_Mhi + (size_t)b * CDIM * CDIM + (size_t)(otile * 128) * CDIM;
    const __nv_bfloat16* Al = g_Mlo + (size_t)b * CDIM * CDIM + (size_t)(otile * 128) * CDIM;
    const __nv_bfloat16* Bh = g_xThi + ((size_t)b * HW + ntile * 128) * CDIM;
    const __nv_bfloat16* Bl = g_xTlo + ((size_t)b * HW + ntile * 128) * CDIM;

    float acc[4][4][4];
#pragma unroll
    for (int i = 0; i < 4; ++i)
#pragma unroll
        for (int j = 0; j < 4; ++j)
#pragma unroll
            for (int k = 0; k < 4; ++k) acc[i][j][k] = 0.f;

    const uint32_t sb = smem_u32(sm);
    issue_stage(sb, Ah, Al, Bh, Bl, CDIM, CDIM, 0, tid);
    CP_COMMIT();

    for (int ch = 0; ch < 12; ++ch) {
        CP_WAIT0();
        __syncthreads();
        if (ch < 11) {
            issue_stage(sb + ((ch + 1) & 1) * STAGE_BYTES, Ah, Al, Bh, Bl,
                        CDIM, CDIM, (ch + 1) * 32, tid);
            CP_COMMIT();
        }
        mma_chunk(sb + (ch & 1) * STAGE_BYTES, lane, wm, wn, acc);
    }

    const int o0 = otile * 128 + wm * 64;
    const int n0 = ntile * 128 + wn * 32;
#pragma unroll
    for (int mi = 0; mi < 4; ++mi)
#pragma unroll
        for (int f = 0; f < 4; ++f) {
            int o = o0 + mi * 16 + (lane >> 2);
            int n = n0 + f * 8 + (lane & 3) * 2;
            *(float2*)&out[((size_t)b * CDIM + o) * HW + n] =
                make_float2(acc[mi][f][0], acc[mi][f][1]);
            *(float2*)&out[((size_t)b * CDIM + o + 8) * HW + n] =
                make_float2(acc[mi][f][2], acc[mi][f][3]);
        }
}

// ---------------- fp32 SIMT tail ----------------
__device__ __forceinline__ unsigned long long dupf2(float x) {
    unsigned long long r;
    asm("mov.b64 %0, {%1, %1};" : "=l"(r) : "f"(x));
    return r;
}
__device__ __forceinline__ void ffma2(unsigned long long& acc,
                                      unsigned long long a, unsigned long long b) {
    asm("fma.rn.f32x2 %0, %1, %2, %0;" : "+l"(acc) : "l"(a), "l"(b));
}
__device__ __forceinline__ float lo_f(unsigned long long v) {
    return __uint_as_float((unsigned)(v & 0xffffffffull));
}
__device__ __forceinline__ float hi_f(unsigned long long v) {
    return __uint_as_float((unsigned)(v >> 32));
}

// mode2=0 (blockIdx.z selects): Rq=wq·G / Rk=wk·G.  mode2=1: Mhi/Mlo = bf16(wo·Bs).
__global__ __launch_bounds__(256) void small_gemm(const float* __restrict__ A0,
                                                  const float* __restrict__ A1, int mode2)
{
    const int m0 = (blockIdx.x % 6) * 64;
    const int n0 = (blockIdx.x / 6) * 64;
    const size_t z = blockIdx.y;
    const size_t CC = (size_t)CDIM * CDIM;
    const int which = blockIdx.z;

    const float* __restrict__ A = mode2 ? A0 : (which ? A1 : A0);
    const float* __restrict__ B = (mode2 ? g_Bs : g_G) + z * CC;

    __shared__ float Asm[16][68];
    __shared__ float Bsm[16][64];

    const int tid = threadIdx.x;
    const int arow = tid >> 2, akc = (tid & 3) * 4;
    const int bkr = tid >> 4, bcol = (tid & 15) * 4;
    const int ty = tid >> 4, tx = tid & 15;

    unsigned long long acc2[4][2];
#pragma unroll
    for (int i = 0; i < 4; ++i) { acc2[i][0] = 0ull; acc2[i][1] = 0ull; }

    for (int k0 = 0; k0 < CDIM; k0 += 16) {
        float4 a4 = *(const float4*)(A + (size_t)(m0 + arow) * CDIM + k0 + akc);
        Asm[akc + 0][arow] = a4.x; Asm[akc + 1][arow] = a4.y;
        Asm[akc + 2][arow] = a4.z; Asm[akc + 3][arow] = a4.w;
        *(float4*)&Bsm[bkr][bcol] = *(const float4*)(B + (size_t)(k0 + bkr) * CDIM + n0 + bcol);
        __syncthreads();
#pragma unroll
        for (int kk = 0; kk < 16; ++kk) {
            const unsigned long long* bp = (const unsigned long long*)&Bsm[kk][tx * 4];
            unsigned long long b20 = bp[0], b21 = bp[1];
#pragma unroll
            for (int i = 0; i < 4; ++i) {
                unsigned long long a2 = dupf2(Asm[kk][ty * 4 + i]);
                ffma2(acc2[i][0], a2, b20);
                ffma2(acc2[i][1], a2, b21);
            }
        }
        __syncthreads();
    }

    if (!mode2) {
        float* C = (which ? g_Rk : g_Rq) + z * CC;
#pragma unroll
        for (int i = 0; i < 4; ++i) {
            unsigned long long* cp =
                (unsigned long long*)&C[(size_t)(m0 + ty * 4 + i) * CDIM + n0 + tx * 4];
            cp[0] = acc2[i][0];
            cp[1] = acc2[i][1];
        }
    } else {
#pragma unroll
        for (int i = 0; i < 4; ++i) {
            float v[4] = {lo_f(acc2[i][0]), hi_f(acc2[i][0]),
                          lo_f(acc2[i][1]), hi_f(acc2[i][1])};
            __align__(8) __nv_bfloat16 hh[4], ll[4];
#pragma unroll
            for (int j = 0; j < 4; ++j) {
                __nv_bfloat16 h = __float2bfloat16(v[j]);
                hh[j] = h;
                ll[j] = __float2bfloat16(v[j] - __bfloat162float(h));
            }
            size_t o = z * CC + (size_t)(m0 + ty * 4 + i) * CDIM + n0 + tx * 4;
            *(uint2*)(g_Mhi + o) = *(const uint2*)hh;
            *(uint2*)(g_Mlo + o) = *(const uint2*)ll;
        }
    }
}

__global__ void norms_kernel(const float* __restrict__ wq, const float* __restrict__ wk) {
    const int which = blockIdx.x;
    const int b = blockIdx.y;
    const float* R = (which ? g_Rk : g_Rq) + (size_t)b * CDIM * CDIM;
    const float* W = which ? wk : wq;
    float* inv = (which ? g_invk : g_invq) + b * CDIM;
    const int lane = threadIdx.x & 31;
    const int wd = threadIdx.x >> 5;
    for (int r = wd; r < CDIM; r += 12) {
        float s = 0.f;
        for (int j = lane; j < CDIM; j += 32)
            s = fmaf(R[(size_t)r * CDIM + j], W[(size_t)r * CDIM + j], s);
#pragma unroll
        for (int o = 16; o; o >>= 1) s += __shfl_xor_sync(0xffffffffu, s, o);
        if (lane == 0) inv[r] = 1.f / fmaxf(sqrtf(fmaxf(s, 0.f)), EPS);
    }
}

__global__ __launch_bounds__(256) void s_kernel(const float* __restrict__ wk) {
    const int bh = blockIdx.x;
    const int b = bh >> 3;
    const int h = bh & 7;
    const int tid = threadIdx.x;

    __shared__ float qs[CH][68];
    __shared__ float ks[CH][68];

    const int c0 = (tid >> 4) * 3;
    const int d0 = (tid & 15) * 3;

    float acc[3][3];
#pragma unroll
    for (int i = 0; i < 3; ++i)
#pragma unroll
        for (int j = 0; j < 3; ++j) acc[i][j] = 0.f;

    const float* Rq = g_Rq + (size_t)b * CDIM * CDIM + (size_t)(h * CH) * CDIM;
    const float* Wk = wk + (size_t)(h * CH) * CDIM;

    for (int ck = 0; ck < 6; ++ck) {
        const int koff = ck * 64;
#pragma unroll
        for (int t = 0; t < 3; ++t) {
            int idx = t * 256 + tid;
            int row = idx >> 4;
            int col = (idx & 15) * 4;
            *(float4*)&qs[row][col] = *(const float4*)(Rq + (size_t)row * CDIM + koff + col);
            *(float4*)&ks[row][col] = *(const float4*)(Wk + (size_t)row * CDIM + koff + col);
        }
        __syncthreads();
#pragma unroll 8
        for (int kk = 0; kk < 64; ++kk) {
            float q0 = qs[c0 + 0][kk], q1 = qs[c0 + 1][kk], q2 = qs[c0 + 2][kk];
            float k0 = ks[d0 + 0][kk], k1 = ks[d0 + 1][kk], k2 = ks[d0 + 2][kk];
            acc[0][0] = fmaf(q0, k0, acc[0][0]);
            acc[0][1] = fmaf(q0, k1, acc[0][1]);
            acc[0][2] = fmaf(q0, k2, acc[0][2]);
            acc[1][0] = fmaf(q1, k0, acc[1][0]);
            acc[1][1] = fmaf(q1, k1, acc[1][1]);
            acc[1][2] = fmaf(q1, k2, acc[1][2]);
            acc[2][0] = fmaf(q2, k0, acc[2][0]);
            acc[2][1] = fmaf(q2, k1, acc[2][1]);
            acc[2][2] = fmaf(q2, k2, acc[2][2]);
        }
        __syncthreads();
    }

    float* Sb = g_S + (size_t)bh * CH * CH;
#pragma unroll
    for (int i = 0; i < 3; ++i)
#pragma unroll
        for (int j = 0; j < 3; ++j)
            Sb[(c0 + i) * CH + (d0 + j)] = acc[i][j];
}

__global__ void attn_softmax_kernel(const float* __restrict__ temperature) {
    const int bh = blockIdx.x;
    const int b = bh >> 3;
    const int h = bh & 7;
    const int c = threadIdx.x;
    if (c >= CH) return;

    const float t = temperature[h];
    const float sq = g_invq[b * CDIM + h * CH + c] * t;
    const float* Srow = g_S + (size_t)bh * CH * CH + c * CH;
    const float* ik = g_invk + b * CDIM + h * CH;

    float v[CH];
    float m = -1e30f;
#pragma unroll
    for (int d = 0; d < CH; ++d) {
        v[d] = Srow[d] * sq * ik[d];
        m = fmaxf(m, v[d]);
    }
    float sum = 0.f;
#pragma unroll
    for (int d = 0; d < CH; ++d) {
        v[d] = __expf(v[d] - m);
        sum += v[d];
    }
    float inv = 1.f / sum;
    float* Arow = g_A + (size_t)bh * CH * CH + c * CH;
#pragma unroll
    for (int d = 0; d < CH; ++d) Arow[d] = v[d] * inv;
}

__global__ __launch_bounds__(384) void bstack_kernel(const float* __restrict__ wv) {
    const int bh = blockIdx.x;
    const int b = bh >> 3;
    const int h = bh & 7;

    __shared__ float As[CH * CH];
    const float* Ahp = g_A + (size_t)bh * CH * CH;
    for (int i = threadIdx.x; i < CH * CH; i += 384) As[i] = Ahp[i];
    __syncthreads();

    const int c = threadIdx.x;
    float acc[CH];
#pragma unroll
    for (int i = 0; i < CH; ++i) acc[i] = 0.f;

    const float* wvp = wv + (size_t)(h * CH) * CDIM + c;
    for (int d = 0; d < CH; ++d) {
        float wvv = wvp[(size_t)d * CDIM];
#pragma unroll
        for (int cp = 0; cp < CH; ++cp) acc[cp] = fmaf(As[cp * CH + d], wvv, acc[cp]);
    }
    float* outp = g_Bs + (size_t)b * CDIM * CDIM + (size_t)(h * CH) * CDIM + c;
#pragma unroll
    for (int cp = 0; cp < CH; ++cp) outp[(size_t)cp * CDIM] = acc[cp];
}

// ---------------- launcher ----------------
extern "C" void kernel_launch(void* const* d_in, const int* in_sizes, int n_in,
                              void* d_out, int out_size) {
    const float* x    = (const float*)d_in[0];
    const float* wq   = (const float*)d_in[1];
    const float* wk   = (const float*)d_in[2];
    const float* wv   = (const float*)d_in[3];
    const float* wo   = (const float*)d_in[4];
    const float* temp = (const float*)d_in[5];
    float* out = (float*)d_out;

    cudaFuncSetAttribute(syrk_mma, cudaFuncAttributeMaxDynamicSharedMemorySize, PIPE_SMEM);
    cudaFuncSetAttribute(out_mma, cudaFuncAttributeMaxDynamicSharedMemorySize, PIPE_SMEM);

    const size_t CC = (size_t)CDIM * CDIM;
    const int nG = (int)(((size_t)BATCH * CC + 255) / 256);

    convert_x2<<<dim3(HW / 32, CDIM / 32, BATCH), 128>>>(x);
    zero_G_kernel<<<nG, 256>>>();
    syrk_mma<<<dim3(6, 16, BATCH), 256, PIPE_SMEM>>>();
    mirror_G_kernel<<<nG, 256>>>();

    small_gemm<<<dim3(36, BATCH, 2), 256>>>(wq, wk, 0);   // Rq, Rk

    norms_kernel<<<dim3(2, BATCH), 384>>>(wq, wk);
    s_kernel<<<BATCH * NHEAD, 256>>>(wk);
    attn_softmax_kernel<<<BATCH * NHEAD, 64>>>(temp);
    bstack_kernel<<<BATCH * NHEAD, 384>>>(wv);

    small_gemm<<<dim3(36, BATCH, 1), 256>>>(wo, wo, 1);   // Mhi/Mlo = bf16(wo @ Bs)

    out_mma<<<dim3(HW / 128, 3, BATCH), 256, PIPE_SMEM>>>(out);
}

// round 10
// speedup vs baseline: 5.1987x; 1.0938x over previous
#include <cuda_runtime.h>
#include <cuda_bf16.h>
#include <math.h>
#include <stdint.h>

#define BATCH 8
#define CDIM 384
#define NHEAD 8
#define CH 48
#define HW 16384
#define EPS 1e-12f

// ---------------- warp-MMA + cp.async helpers (plain sm_80+ PTX) ----------------
__device__ __forceinline__ uint32_t smem_u32(const void* p) {
    uint32_t a;
    asm("{ .reg .u64 t; cvta.to.shared.u64 t, %1; cvt.u32.u64 %0, t; }" : "=r"(a) : "l"(p));
    return a;
}
__device__ __forceinline__ void ldm_x4(uint32_t* r, uint32_t addr) {
    asm volatile("ldmatrix.sync.aligned.m8n8.x4.shared.b16 {%0,%1,%2,%3}, [%4];"
                 : "=r"(r[0]), "=r"(r[1]), "=r"(r[2]), "=r"(r[3]) : "r"(addr));
}
__device__ __forceinline__ void ldm_x4_trans(uint32_t* r, uint32_t addr) {
    asm volatile("ldmatrix.sync.aligned.m8n8.x4.trans.shared.b16 {%0,%1,%2,%3}, [%4];"
                 : "=r"(r[0]), "=r"(r[1]), "=r"(r[2]), "=r"(r[3]) : "r"(addr));
}
__device__ __forceinline__ void mma_bf16(float* d, const uint32_t* a, const uint32_t* b) {
    asm volatile(
        "mma.sync.aligned.m16n8k16.row.col.f32.bf16.bf16.f32 "
        "{%0,%1,%2,%3}, {%4,%5,%6,%7}, {%8,%9}, {%0,%1,%2,%3};"
        : "+f"(d[0]), "+f"(d[1]), "+f"(d[2]), "+f"(d[3])
        : "r"(a[0]), "r"(a[1]), "r"(a[2]), "r"(a[3]), "r"(b[0]), "r"(b[1]));
}
__device__ __forceinline__ void cp_async16(uint32_t saddr, const void* gptr) {
    asm volatile("cp.async.cg.shared.global [%0], [%1], 16;" :: "r"(saddr), "l"(gptr));
}
#define CP_COMMIT() asm volatile("cp.async.commit_group;")
#define CP_WAIT0()  asm volatile("cp.async.wait_group 0;")

// ---------------- scratch ----------------
__device__ float g_G [(size_t)BATCH * CDIM * CDIM];
__device__ float g_Rq[(size_t)BATCH * CDIM * CDIM];
__device__ float g_Rk[(size_t)BATCH * CDIM * CDIM];
__device__ float g_invq[BATCH * CDIM];
__device__ float g_invk[BATCH * CDIM];
__device__ float g_S [BATCH * NHEAD * CH * CH];
__device__ float g_A [BATCH * NHEAD * CH * CH];

__device__ __nv_bfloat16 g_xhi [(size_t)BATCH * CDIM * HW];   // [b][c][n]
__device__ __nv_bfloat16 g_xlo [(size_t)BATCH * CDIM * HW];
__device__ __nv_bfloat16 g_Ghi [(size_t)BATCH * CDIM * CDIM];
__device__ __nv_bfloat16 g_Glo [(size_t)BATCH * CDIM * CDIM];
__device__ __nv_bfloat16 g_BsThi[(size_t)BATCH * CDIM * CDIM]; // [b][m][c]
__device__ __nv_bfloat16 g_BsTlo[(size_t)BATCH * CDIM * CDIM];
__device__ __nv_bfloat16 g_Mhi [(size_t)BATCH * CDIM * CDIM];
__device__ __nv_bfloat16 g_Mlo [(size_t)BATCH * CDIM * CDIM];
__device__ __nv_bfloat16 g_Whi [3 * CDIM * CDIM];  // wq, wk, wo hi
__device__ __nv_bfloat16 g_Wlo [3 * CDIM * CDIM];

// ---------------- convert x -> bf16 hi/lo (flat, wide stores) ----------------
__global__ void convert_plain(const float* __restrict__ x) {
    size_t i = ((size_t)blockIdx.x * 256 + threadIdx.x) * 8;
    float4 v0 = *(const float4*)(x + i);
    float4 v1 = *(const float4*)(x + i + 4);
    float v[8] = {v0.x, v0.y, v0.z, v0.w, v1.x, v1.y, v1.z, v1.w};
    __align__(16) __nv_bfloat16 hh[8], ll[8];
#pragma unroll
    for (int j = 0; j < 8; ++j) {
        __nv_bfloat16 h = __float2bfloat16(v[j]);
        hh[j] = h;
        ll[j] = __float2bfloat16(v[j] - __bfloat162float(h));
    }
    *(uint4*)(g_xhi + i) = *(const uint4*)hh;
    *(uint4*)(g_xlo + i) = *(const uint4*)ll;
}

// ---------------- convert weights (wq, wk, wo) -> hi/lo ----------------
__global__ void convert_W(const float* __restrict__ wq, const float* __restrict__ wk,
                          const float* __restrict__ wo) {
    int i = blockIdx.x * 256 + threadIdx.x;
    if (i >= CDIM * CDIM) return;
    const float* srcs[3] = {wq, wk, wo};
#pragma unroll
    for (int m = 0; m < 3; ++m) {
        float v = srcs[m][i];
        __nv_bfloat16 h = __float2bfloat16(v);
        g_Whi[m * CDIM * CDIM + i] = h;
        g_Wlo[m * CDIM * CDIM + i] = __float2bfloat16(v - __bfloat162float(h));
    }
}

__global__ void zero_G_kernel() {
    size_t i = (size_t)blockIdx.x * 256 + threadIdx.x;
    if (i < (size_t)BATCH * CDIM * CDIM) g_G[i] = 0.f;
}

// ---------------- mirror lower tile-triangle of G + convert to hi/lo ----------------
__global__ void mirror_convert_G() {
    size_t i = (size_t)blockIdx.x * 256 + threadIdx.x;
    if (i >= (size_t)BATCH * CDIM * CDIM) return;
    size_t bb = i / (CDIM * CDIM);
    int rc = (int)(i % (CDIM * CDIM));
    int r = rc / CDIM, c = rc % CDIM;
    float v;
    if ((r >> 7) > (c >> 7)) {
        v = g_G[bb * CDIM * CDIM + (size_t)c * CDIM + r];
        g_G[i] = v;
    } else {
        v = g_G[i];
    }
    __nv_bfloat16 h = __float2bfloat16(v);
    g_Ghi[i] = h;
    g_Glo[i] = __float2bfloat16(v - __bfloat162float(h));
}

// ---------------- MMA tile geometry (k-contiguous operand pairs) ----------------
#define ROWB 80
#define TILE_BYTES (128 * ROWB)
#define OFF_AH 0
#define OFF_AL (1 * TILE_BYTES)
#define OFF_BH (2 * TILE_BYTES)
#define OFF_BL (3 * TILE_BYTES)
#define STAGE_BYTES (4 * TILE_BYTES)   // 40960
#define PIPE_SMEM (2 * STAGE_BYTES)    // 81920

__device__ __forceinline__ void issue_stage(uint32_t sdst,
    const __nv_bfloat16* Ah, const __nv_bfloat16* Al,
    const __nv_bfloat16* Bh, const __nv_bfloat16* Bl,
    size_t strideA, size_t strideB, int k0, int tid)
{
#pragma unroll
    for (int t = 0; t < 2; ++t) {
        int idx = t * 256 + tid;
        int r = idx >> 2, g = idx & 3;
        uint32_t so = (uint32_t)(r * ROWB + g * 16);
        size_t goA = (size_t)r * strideA + k0 + g * 8;
        size_t goB = (size_t)r * strideB + k0 + g * 8;
        cp_async16(sdst + OFF_AH + so, Ah + goA);
        cp_async16(sdst + OFF_AL + so, Al + goA);
        cp_async16(sdst + OFF_BH + so, Bh + goB);
        cp_async16(sdst + OFF_BL + so, Bl + goB);
    }
}

__device__ __forceinline__ void mma_chunk(uint32_t sbase, int lane, int wm, int wn,
                                          float acc[4][4][4]) {
#pragma unroll
    for (int kk = 0; kk < 2; ++kk) {
        uint32_t a_hi[4][4], a_lo[4][4], b_hi[2][4], b_lo[2][4];
        const uint32_t arow = (uint32_t)(wm * 64 + (lane & 15));
        const uint32_t acol = ((lane >> 4) * 16) + kk * 32;
#pragma unroll
        for (int mi = 0; mi < 4; ++mi) {
            uint32_t off = (arow + mi * 16) * ROWB + acol;
            ldm_x4(a_hi[mi], sbase + OFF_AH + off);
            ldm_x4(a_lo[mi], sbase + OFF_AL + off);
        }
        const uint32_t brow = (uint32_t)(wn * 32 + ((lane >> 4) << 3) + (lane & 7));
        const uint32_t bcol = (((lane >> 3) & 1) * 16) + kk * 32;
#pragma unroll
        for (int nj = 0; nj < 2; ++nj) {
            uint32_t off = (brow + nj * 16) * ROWB + bcol;
            ldm_x4(b_hi[nj], sbase + OFF_BH + off);
            ldm_x4(b_lo[nj], sbase + OFF_BL + off);
        }
#pragma unroll
        for (int mi = 0; mi < 4; ++mi)
#pragma unroll
            for (int nj = 0; nj < 2; ++nj) {
                mma_bf16(acc[mi][nj * 2 + 0], a_hi[mi], &b_hi[nj][0]);
                mma_bf16(acc[mi][nj * 2 + 1], a_hi[mi], &b_hi[nj][2]);
                mma_bf16(acc[mi][nj * 2 + 0], a_hi[mi], &b_lo[nj][0]);
                mma_bf16(acc[mi][nj * 2 + 1], a_hi[mi], &b_lo[nj][2]);
                mma_bf16(acc[mi][nj * 2 + 0], a_lo[mi], &b_hi[nj][0]);
                mma_bf16(acc[mi][nj * 2 + 1], a_lo[mi], &b_hi[nj][2]);
            }
    }
}

// ---------------- syrk: G += x x^T (single-barrier pipeline) ----------------
__global__ __launch_bounds__(256) void syrk_mma() {
    extern __shared__ __align__(16) char sm[];
    const int tid = threadIdx.x, lane = tid & 31, wid = tid >> 5;
    const int wm = wid & 1, wn = wid >> 1;
    const int TI[6] = {0, 0, 0, 1, 1, 2};
    const int TJ[6] = {0, 1, 2, 1, 2, 2};
    const int ti = TI[blockIdx.x], tj = TJ[blockIdx.x];
    const int b = blockIdx.z;
    const int kb = blockIdx.y * 1024;

    const __nv_bfloat16* Ah = g_xhi + ((size_t)(b * CDIM + ti * 128)) * HW;
    const __nv_bfloat16* Al = g_xlo + ((size_t)(b * CDIM + ti * 128)) * HW;
    const __nv_bfloat16* Bh = g_xhi + ((size_t)(b * CDIM + tj * 128)) * HW;
    const __nv_bfloat16* Bl = g_xlo + ((size_t)(b * CDIM + tj * 128)) * HW;

    float acc[4][4][4];
#pragma unroll
    for (int i = 0; i < 4; ++i)
#pragma unroll
        for (int j = 0; j < 4; ++j)
#pragma unroll
            for (int k = 0; k < 4; ++k) acc[i][j][k] = 0.f;

    const uint32_t sb = smem_u32(sm);
    issue_stage(sb, Ah, Al, Bh, Bl, HW, HW, kb, tid);
    CP_COMMIT();

    for (int ch = 0; ch < 32; ++ch) {
        CP_WAIT0();
        __syncthreads();
        if (ch < 31) {
            issue_stage(sb + ((ch + 1) & 1) * STAGE_BYTES, Ah, Al, Bh, Bl,
                        HW, HW, kb + (ch + 1) * 32, tid);
            CP_COMMIT();
        }
        mma_chunk(sb + (ch & 1) * STAGE_BYTES, lane, wm, wn, acc);
    }

    float* Gp = g_G + (size_t)b * CDIM * CDIM;
    const int r0 = ti * 128 + wm * 64;
    const int c0 = tj * 128 + wn * 32;
#pragma unroll
    for (int mi = 0; mi < 4; ++mi)
#pragma unroll
        for (int f = 0; f < 4; ++f) {
            int row = r0 + mi * 16 + (lane >> 2);
            int col = c0 + f * 8 + (lane & 3) * 2;
            atomicAdd(&Gp[(size_t)row * CDIM + col],           acc[mi][f][0]);
            atomicAdd(&Gp[(size_t)row * CDIM + col + 1],       acc[mi][f][1]);
            atomicAdd(&Gp[(size_t)(row + 8) * CDIM + col],     acc[mi][f][2]);
            atomicAdd(&Gp[(size_t)(row + 8) * CDIM + col + 1], acc[mi][f][3]);
        }
}

// ---------------- wgemm: C = W-split @ B-split, 384x384 per batch ----------------
// mode 0: A = wq/wk (blockIdx.z), B = Ghi/Glo rows (symmetry), C fp32 -> Rq/Rk
// mode 1: A = wo, B = BsT hi/lo, C -> Mhi/Mlo (bf16 split)
__global__ __launch_bounds__(256) void wgemm_mma(int mode) {
    extern __shared__ __align__(16) char sm[];
    const int tid = threadIdx.x, lane = tid & 31, wid = tid >> 5;
    const int wm = wid & 1, wn = wid >> 1;
    const int o0 = (blockIdx.x % 3) * 128;
    const int j0 = (blockIdx.x / 3) * 128;
    const int b = blockIdx.y;
    const int which = blockIdx.z;   // mode 0: 0=q, 1=k
    const size_t CC = (size_t)CDIM * CDIM;

    const int widx = mode ? 2 : which;
    const __nv_bfloat16* Ah = g_Whi + (size_t)widx * CC + (size_t)o0 * CDIM;
    const __nv_bfloat16* Al = g_Wlo + (size_t)widx * CC + (size_t)o0 * CDIM;
    const __nv_bfloat16* Bh = (mode ? g_BsThi : g_Ghi) + (size_t)b * CC + (size_t)j0 * CDIM;
    const __nv_bfloat16* Bl = (mode ? g_BsTlo : g_Glo) + (size_t)b * CC + (size_t)j0 * CDIM;

    float acc[4][4][4];
#pragma unroll
    for (int i = 0; i < 4; ++i)
#pragma unroll
        for (int j = 0; j < 4; ++j)
#pragma unroll
            for (int k = 0; k < 4; ++k) acc[i][j][k] = 0.f;

    const uint32_t sb = smem_u32(sm);
    issue_stage(sb, Ah, Al, Bh, Bl, CDIM, CDIM, 0, tid);
    CP_COMMIT();

    for (int ch = 0; ch < 12; ++ch) {
        CP_WAIT0();
        __syncthreads();
        if (ch < 11) {
            issue_stage(sb + ((ch + 1) & 1) * STAGE_BYTES, Ah, Al, Bh, Bl,
                        CDIM, CDIM, (ch + 1) * 32, tid);
            CP_COMMIT();
        }
        mma_chunk(sb + (ch & 1) * STAGE_BYTES, lane, wm, wn, acc);
    }

    if (mode == 0) {
        float* C = (which ? g_Rk : g_Rq) + b * CC;
#pragma unroll
        for (int mi = 0; mi < 4; ++mi)
#pragma unroll
            for (int f = 0; f < 4; ++f) {
                int o = o0 + wm * 64 + mi * 16 + (lane >> 2);
                int j = j0 + wn * 32 + f * 8 + (lane & 3) * 2;
                *(float2*)&C[(size_t)o * CDIM + j] =
                    make_float2(acc[mi][f][0], acc[mi][f][1]);
                *(float2*)&C[(size_t)(o + 8) * CDIM + j] =
                    make_float2(acc[mi][f][2], acc[mi][f][3]);
            }
    } else {
#pragma unroll
        for (int mi = 0; mi < 4; ++mi)
#pragma unroll
            for (int f = 0; f < 4; ++f) {
                int o = o0 + wm * 64 + mi * 16 + (lane >> 2);
                int j = j0 + wn * 32 + f * 8 + (lane & 3) * 2;
#pragma unroll
                for (int half = 0; half < 2; ++half) {
                    float v0 = acc[mi][f][half * 2 + 0];
                    float v1 = acc[mi][f][half * 2 + 1];
                    __nv_bfloat16 h0 = __float2bfloat16(v0);
                    __nv_bfloat16 h1 = __float2bfloat16(v1);
                    __nv_bfloat16 l0 = __float2bfloat16(v0 - __bfloat162float(h0));
                    __nv_bfloat16 l1 = __float2bfloat16(v1 - __bfloat162float(h1));
                    size_t off = b * CC + (size_t)(o + half * 8) * CDIM + j;
                    *(__nv_bfloat162*)(g_Mhi + off) = __nv_bfloat162(h0, h1);
                    *(__nv_bfloat162*)(g_Mlo + off) = __nv_bfloat162(l0, l1);
                }
            }
    }
}

// ---------------- out = M @ x: B read from PLAIN x via ldmatrix.trans ----------------
#define O_BROWB 272
#define O_AH 0
#define O_AL 10240
#define O_BH 20480
#define O_BL (20480 + 32 * O_BROWB)     // 29184
#define O_STAGE (O_BL + 32 * O_BROWB)   // 37888
#define OUT_SMEM (2 * O_STAGE)          // 75776

__global__ __launch_bounds__(256) void out_mma(float* __restrict__ out) {
    extern __shared__ __align__(16) char sm[];
    const int tid = threadIdx.x, lane = tid & 31, wid = tid >> 5;
    const int wm = wid & 1, wn = wid >> 1;
    const int ntile = blockIdx.x;
    const int otile = blockIdx.y;
    const int b = blockIdx.z;
    const size_t CC = (size_t)CDIM * CDIM;

    const __nv_bfloat16* Ah = g_Mhi + (size_t)b * CC + (size_t)(otile * 128) * CDIM;
    const __nv_bfloat16* Al = g_Mlo + (size_t)b * CC + (size_t)(otile * 128) * CDIM;
    const __nv_bfloat16* Xh = g_xhi + (size_t)b * CDIM * HW + (size_t)ntile * 128;
    const __nv_bfloat16* Xl = g_xlo + (size_t)b * CDIM * HW + (size_t)ntile * 128;

    float acc[4][4][4];
#pragma unroll
    for (int i = 0; i < 4; ++i)
#pragma unroll
        for (int j = 0; j < 4; ++j)
#pragma unroll
            for (int k = 0; k < 4; ++k) acc[i][j][k] = 0.f;

    const uint32_t sb = smem_u32(sm);

    // stage issue: A = M tile 128o x 32c (ROWB rows); B = x tile 32c x 128n (O_BROWB rows)
    auto issue = [&](uint32_t sdst, int cbase) {
#pragma unroll
        for (int t = 0; t < 2; ++t) {
            int idx = t * 256 + tid;
            {   // A: r=0..127 rows (o), g=0..3 (16B groups of c)
                int r = idx >> 2, g = idx & 3;
                uint32_t so = (uint32_t)(r * ROWB + g * 16);
                size_t go = (size_t)r * CDIM + cbase + g * 8;
                cp_async16(sdst + O_AH + so, Ah + go);
                cp_async16(sdst + O_AL + so, Al + go);
            }
            {   // B: r=0..31 rows (c), c16=0..15 (16B groups of n)
                int r = idx >> 4, c16 = idx & 15;
                uint32_t so = (uint32_t)(r * O_BROWB + c16 * 16);
                size_t go = (size_t)(cbase + r) * HW + c16 * 8;
                cp_async16(sdst + O_BH + so, Xh + go);
                cp_async16(sdst + O_BL + so, Xl + go);
            }
        }
    };

    issue(sb, 0);
    CP_COMMIT();

    for (int ch = 0; ch < 12; ++ch) {
        CP_WAIT0();
        __syncthreads();
        if (ch < 11) {
            issue(sb + ((ch + 1) & 1) * O_STAGE, (ch + 1) * 32);
            CP_COMMIT();
        }
        const uint32_t sbase = sb + (ch & 1) * O_STAGE;
#pragma unroll
        for (int kk = 0; kk < 2; ++kk) {
            uint32_t a_hi[4][4], a_lo[4][4], b_hi[2][4], b_lo[2][4];
            const uint32_t arow = (uint32_t)(wm * 64 + (lane & 15));
            const uint32_t acol = ((lane >> 4) * 16) + kk * 32;
#pragma unroll
            for (int mi = 0; mi < 4; ++mi) {
                uint32_t off = (arow + mi * 16) * ROWB + acol;
                ldm_x4(a_hi[mi], sbase + O_AH + off);
                ldm_x4(a_lo[mi], sbase + O_AL + off);
            }
            // B via trans: rows = c (k), cols = n
            const uint32_t brow = (uint32_t)(kk * 16 + (lane & 7) + ((lane >> 3) & 1) * 8);
#pragma unroll
            for (int nj = 0; nj < 2; ++nj) {
                uint32_t bcol = (uint32_t)(wn * 32 + nj * 16 + (lane >> 4) * 8) * 2;
                uint32_t off = brow * O_BROWB + bcol;
                ldm_x4_trans(b_hi[nj], sbase + O_BH + off);
                ldm_x4_trans(b_lo[nj], sbase + O_BL + off);
            }
#pragma unroll
            for (int mi = 0; mi < 4; ++mi)
#pragma unroll
                for (int nj = 0; nj < 2; ++nj) {
                    mma_bf16(acc[mi][nj * 2 + 0], a_hi[mi], &b_hi[nj][0]);
                    mma_bf16(acc[mi][nj * 2 + 1], a_hi[mi], &b_hi[nj][2]);
                    mma_bf16(acc[mi][nj * 2 + 0], a_hi[mi], &b_lo[nj][0]);
                    mma_bf16(acc[mi][nj * 2 + 1], a_hi[mi], &b_lo[nj][2]);
                    mma_bf16(acc[mi][nj * 2 + 0], a_lo[mi], &b_hi[nj][0]);
                    mma_bf16(acc[mi][nj * 2 + 1], a_lo[mi], &b_hi[nj][2]);
                }
        }
    }

    const int o0 = otile * 128 + wm * 64;
    const int n0 = ntile * 128 + wn * 32;
#pragma unroll
    for (int mi = 0; mi < 4; ++mi)
#pragma unroll
        for (int f = 0; f < 4; ++f) {
            int o = o0 + mi * 16 + (lane >> 2);
            int n = n0 + f * 8 + (lane & 3) * 2;
            *(float2*)&out[((size_t)b * CDIM + o) * HW + n] =
                make_float2(acc[mi][f][0], acc[mi][f][1]);
            *(float2*)&out[((size_t)b * CDIM + o + 8) * HW + n] =
                make_float2(acc[mi][f][2], acc[mi][f][3]);
        }
}

// ---------------- fp32 SIMT tail ----------------
__global__ void norms_kernel(const float* __restrict__ wq, const float* __restrict__ wk) {
    const int which = blockIdx.x;
    const int b = blockIdx.y;
    const float* R = (which ? g_Rk : g_Rq) + (size_t)b * CDIM * CDIM;
    const float* W = which ? wk : wq;
    float* inv = (which ? g_invk : g_invq) + b * CDIM;
    const int lane = threadIdx.x & 31;
    const int wd = threadIdx.x >> 5;
    for (int r = wd; r < CDIM; r += 12) {
        float s = 0.f;
        for (int j = lane; j < CDIM; j += 32)
            s = fmaf(R[(size_t)r * CDIM + j], W[(size_t)r * CDIM + j], s);
#pragma unroll
        for (int o = 16; o; o >>= 1) s += __shfl_xor_sync(0xffffffffu, s, o);
        if (lane == 0) inv[r] = 1.f / fmaxf(sqrtf(fmaxf(s, 0.f)), EPS);
    }
}

__global__ __launch_bounds__(256) void s_kernel(const float* __restrict__ wk) {
    const int bh = blockIdx.x;
    const int b = bh >> 3;
    const int h = bh & 7;
    const int tid = threadIdx.x;

    __shared__ float qs[CH][68];
    __shared__ float ks[CH][68];

    const int c0 = (tid >> 4) * 3;
    const int d0 = (tid & 15) * 3;

    float acc[3][3];
#pragma unroll
    for (int i = 0; i < 3; ++i)
#pragma unroll
        for (int j = 0; j < 3; ++j) acc[i][j] = 0.f;

    const float* Rq = g_Rq + (size_t)b * CDIM * CDIM + (size_t)(h * CH) * CDIM;
    const float* Wk = wk + (size_t)(h * CH) * CDIM;

    for (int ck = 0; ck < 6; ++ck) {
        const int koff = ck * 64;
#pragma unroll
        for (int t = 0; t < 3; ++t) {
            int idx = t * 256 + tid;
            int row = idx >> 4;
            int col = (idx & 15) * 4;
            *(float4*)&qs[row][col] = *(const float4*)(Rq + (size_t)row * CDIM + koff + col);
            *(float4*)&ks[row][col] = *(const float4*)(Wk + (size_t)row * CDIM + koff + col);
        }
        __syncthreads();
#pragma unroll 8
        for (int kk = 0; kk < 64; ++kk) {
            float q0 = qs[c0 + 0][kk], q1 = qs[c0 + 1][kk], q2 = qs[c0 + 2][kk];
            float k0 = ks[d0 + 0][kk], k1 = ks[d0 + 1][kk], k2 = ks[d0 + 2][kk];
            acc[0][0] = fmaf(q0, k0, acc[0][0]);
            acc[0][1] = fmaf(q0, k1, acc[0][1]);
            acc[0][2] = fmaf(q0, k2, acc[0][2]);
            acc[1][0] = fmaf(q1, k0, acc[1][0]);
            acc[1][1] = fmaf(q1, k1, acc[1][1]);
            acc[1][2] = fmaf(q1, k2, acc[1][2]);
            acc[2][0] = fmaf(q2, k0, acc[2][0]);
            acc[2][1] = fmaf(q2, k1, acc[2][1]);
            acc[2][2] = fmaf(q2, k2, acc[2][2]);
        }
        __syncthreads();
    }

    float* Sb = g_S + (size_t)bh * CH * CH;
#pragma unroll
    for (int i = 0; i < 3; ++i)
#pragma unroll
        for (int j = 0; j < 3; ++j)
            Sb[(c0 + i) * CH + (d0 + j)] = acc[i][j];
}

__global__ void attn_softmax_kernel(const float* __restrict__ temperature) {
    const int bh = blockIdx.x;
    const int b = bh >> 3;
    const int h = bh & 7;
    const int c = threadIdx.x;
    if (c >= CH) return;

    const float t = temperature[h];
    const float sq = g_invq[b * CDIM + h * CH + c] * t;
    const float* Srow = g_S + (size_t)bh * CH * CH + c * CH;
    const float* ik = g_invk + b * CDIM + h * CH;

    float v[CH];
    float m = -1e30f;
#pragma unroll
    for (int d = 0; d < CH; ++d) {
        v[d] = Srow[d] * sq * ik[d];
        m = fmaxf(m, v[d]);
    }
    float sum = 0.f;
#pragma unroll
    for (int d = 0; d < CH; ++d) {
        v[d] = __expf(v[d] - m);
        sum += v[d];
    }
    float inv = 1.f / sum;
    float* Arow = g_A + (size_t)bh * CH * CH + c * CH;
#pragma unroll
    for (int d = 0; d < CH; ++d) Arow[d] = v[d] * inv;
}

// ---------------- BsT rows [m][h*48..+48) = (A_h @ Wv)^T, stored as bf16 hi/lo ----------------
__global__ __launch_bounds__(384) void bstack_T(const float* __restrict__ wv) {
    const int bh = blockIdx.x;
    const int b = bh >> 3;
    const int h = bh & 7;

    __shared__ float As[CH * CH];
    const float* Ahp = g_A + (size_t)bh * CH * CH;
    for (int i = threadIdx.x; i < CH * CH; i += 384) As[i] = Ahp[i];
    __syncthreads();

    const int m = threadIdx.x;  // output column 0..383
    float acc[CH];
#pragma unroll
    for (int i = 0; i < CH; ++i) acc[i] = 0.f;

    const float* wvp = wv + (size_t)(h * CH) * CDIM + m;
    for (int d = 0; d < CH; ++d) {
        float wvv = wvp[(size_t)d * CDIM];
#pragma unroll
        for (int cp = 0; cp < CH; ++cp) acc[cp] = fmaf(As[cp * CH + d], wvv, acc[cp]);
    }
    // BsT[m][h*48 + cp] = acc[cp]
    size_t base = ((size_t)b * CDIM + m) * CDIM + h * CH;
    __align__(16) __nv_bfloat16 hh[CH], ll[CH];
#pragma unroll
    for (int cp = 0; cp < CH; ++cp) {
        __nv_bfloat16 hv = __float2bfloat16(acc[cp]);
        hh[cp] = hv;
        ll[cp] = __float2bfloat16(acc[cp] - __bfloat162float(hv));
    }
#pragma unroll
    for (int q = 0; q < CH / 4; ++q) {
        *(uint2*)(g_BsThi + base + q * 4) = *(const uint2*)(hh + q * 4);
        *(uint2*)(g_BsTlo + base + q * 4) = *(const uint2*)(ll + q * 4);
    }
}

// ---------------- launcher ----------------
extern "C" void kernel_launch(void* const* d_in, const int* in_sizes, int n_in,
                              void* d_out, int out_size) {
    const float* x    = (const float*)d_in[0];
    const float* wq   = (const float*)d_in[1];
    const float* wk   = (const float*)d_in[2];
    const float* wv   = (const float*)d_in[3];
    const float* wo   = (const float*)d_in[4];
    const float* temp = (const float*)d_in[5];
    float* out = (float*)d_out;

    cudaFuncSetAttribute(syrk_mma, cudaFuncAttributeMaxDynamicSharedMemorySize, PIPE_SMEM);
    cudaFuncSetAttribute(wgemm_mma, cudaFuncAttributeMaxDynamicSharedMemorySize, PIPE_SMEM);
    cudaFuncSetAttribute(out_mma, cudaFuncAttributeMaxDynamicSharedMemorySize, OUT_SMEM);

    const size_t CC = (size_t)CDIM * CDIM;
    const int nG = (int)(((size_t)BATCH * CC + 255) / 256);

    convert_plain<<<24576, 256>>>(x);
    convert_W<<<(CDIM * CDIM + 255) / 256, 256>>>(wq, wk, wo);
    zero_G_kernel<<<nG, 256>>>();
    syrk_mma<<<dim3(6, 16, BATCH), 256, PIPE_SMEM>>>();
    mirror_convert_G<<<nG, 256>>>();

    wgemm_mma<<<dim3(9, BATCH, 2), 256, PIPE_SMEM>>>(0);   // Rq, Rk (fp32)

    norms_kernel<<<dim3(2, BATCH), 384>>>(wq, wk);
    s_kernel<<<BATCH * NHEAD, 256>>>(wk);
    attn_softmax_kernel<<<BATCH * NHEAD, 64>>>(temp);
    bstack_T<<<BATCH * NHEAD, 384>>>(wv);

    wgemm_mma<<<dim3(9, BATCH, 1), 256, PIPE_SMEM>>>(1);   // Mhi/Mlo

    out_mma<<<dim3(HW / 128, 3, BATCH), 256, OUT_SMEM>>>(out);
}